// round 1
// baseline (speedup 1.0000x reference)
#include <cuda_runtime.h>
#include <cstdint>

#define D      256
#define N1C    50000
#define E1C    800000
#define NDRUG  4096
#define E2C    131072
#define DD     (D*D)

// ---------------- scratch (device globals; no allocation allowed) -------------
__device__ float g_x[(size_t)N1C * D];
__device__ float g_y[(size_t)N1C * D];
__device__ float g_agg[(size_t)N1C * D];
__device__ float g_cnt1[N1C];
__device__ float g_gmax[NDRUG * D];
__device__ float g_gsum[NDRUG * D];
__device__ float g_cntb[NDRUG];
__device__ float g_cnt2[NDRUG];
__device__ float g_xdrug[NDRUG * D];
__device__ float g_x2a[NDRUG * D];
__device__ float g_x2b[NDRUG * D];
__device__ float g_agg2[NDRUG * D];

// ---------------- kernels ----------------------------------------------------

// out[i,:] = emb[ids[i],:]   (one float4 per thread, 64 threads per row)
__global__ void gather_rows(const float* __restrict__ emb, const int* __restrict__ ids,
                            float* __restrict__ out, int n) {
    int t = blockIdx.x * blockDim.x + threadIdx.x;
    int i = t >> 6, c = t & 63;
    if (i >= n) return;
    float4 v = ((const float4*)(emb + (size_t)ids[i] * D))[c];
    ((float4*)(out + (size_t)i * D))[c] = v;
}

// x2 init: xDrug rows for ids < NDRUG, emb2 rows otherwise
__global__ void gather2_rows(const float* __restrict__ xdrug, const float* __restrict__ emb2,
                             const int* __restrict__ ids, float* __restrict__ out) {
    int t = blockIdx.x * blockDim.x + threadIdx.x;
    int i = t >> 6, c = t & 63;
    if (i >= NDRUG) return;
    int id = ids[i];
    const float* src = (id < NDRUG) ? (xdrug + (size_t)id * D) : (emb2 + (size_t)id * D);
    ((float4*)(out + (size_t)i * D))[c] = ((const float4*)src)[c];
}

__global__ void count_dst(const int* __restrict__ dst, float* __restrict__ cnt, int n) {
    int e = blockIdx.x * blockDim.x + threadIdx.x;
    if (e < n) atomicAdd(&cnt[dst[e]], 1.0f);
}

__global__ void recip_clamp(float* __restrict__ cnt, int n) {
    int i = blockIdx.x * blockDim.x + threadIdx.x;
    if (i < n) cnt[i] = 1.0f / fmaxf(cnt[i], 1.0f);
}

// agg[dst[e],:] += x[src[e],:]
__global__ void edge_scatter(const float* __restrict__ x, const int* __restrict__ src,
                             const int* __restrict__ dst, float* __restrict__ agg, int E) {
    int t = blockIdx.x * blockDim.x + threadIdx.x;
    int e = t >> 6, c = t & 63;
    if (e >= E) return;
    int s = src[e], d = dst[e];
    float4 v = ((const float4*)(x + (size_t)s * D))[c];
    float* a = agg + (size_t)d * D + c * 4;
    atomicAdd(a + 0, v.x);
    atomicAdd(a + 1, v.y);
    atomicAdd(a + 2, v.z);
    atomicAdd(a + 3, v.w);
}

// a[i,:] *= recip[i]
__global__ void scale_rows(float* __restrict__ a, const float* __restrict__ recip, int n) {
    int t = blockIdx.x * blockDim.x + threadIdx.x;
    int i = t >> 6, c = t & 63;
    if (i >= n) return;
    float r = recip[i];
    float4* p = (float4*)(a + (size_t)i * D) + c;
    float4 v = *p;
    v.x *= r; v.y *= r; v.z *= r; v.w *= r;
    *p = v;
}

// segment max (values >= 0, int-compare valid) + segment sum, over sorted-or-not batch ids
__global__ void pool_kernel(const float* __restrict__ x, const int* __restrict__ batch,
                            float* __restrict__ gmax, float* __restrict__ gsum, int n) {
    int t = blockIdx.x * blockDim.x + threadIdx.x;
    int i = t >> 6, c = t & 63;
    if (i >= n) return;
    int b = batch[i];
    float4 v = ((const float4*)(x + (size_t)i * D))[c];
    int* pm = (int*)(gmax + (size_t)b * D + c * 4);
    float* ps = gsum + (size_t)b * D + c * 4;
    atomicMax(pm + 0, __float_as_int(v.x));
    atomicMax(pm + 1, __float_as_int(v.y));
    atomicMax(pm + 2, __float_as_int(v.z));
    atomicMax(pm + 3, __float_as_int(v.w));
    atomicAdd(ps + 0, v.x);
    atomicAdd(ps + 1, v.y);
    atomicAdd(ps + 2, v.z);
    atomicAdd(ps + 3, v.w);
}

// C[M,256] = relu( sum_s A_s[M,256] @ B_s[256,256] + bias ), up to 3 segments.
// BM=64, BN=64, BK=16, 128 threads, 4x8 microtile per thread.
__global__ void __launch_bounds__(128) gemm3(
    const float* A0, const float* B0,
    const float* A1, const float* B1,
    const float* A2, const float* B2,
    const float* __restrict__ bias,
    float* __restrict__ C, int M) {
    __shared__ float As[16][68];
    __shared__ float Bs[16][64];
    const int tid = threadIdx.x;
    const int m0 = blockIdx.y * 64;
    const int n0 = blockIdx.x * 64;
    const int tm = (tid >> 3) * 4;   // 0..60
    const int tn = (tid & 7) * 8;    // 0..56

    float acc[4][8];
#pragma unroll
    for (int r = 0; r < 4; r++)
#pragma unroll
        for (int c = 0; c < 8; c++) acc[r][c] = 0.f;

    const float* Aseg[3] = {A0, A1, A2};
    const float* Bseg[3] = {B0, B1, B2};

    for (int s = 0; s < 3; s++) {
        const float* A = Aseg[s];
        const float* B = Bseg[s];
        if (!A) break;
        for (int k0 = 0; k0 < D; k0 += 16) {
            // A tile: 64 rows x 16 cols, store transposed As[k][m]
#pragma unroll
            for (int l = 0; l < 2; l++) {
                int q = tid + l * 128;       // 0..255 float4 slots
                int row = q >> 2;            // 0..63
                int kf = q & 3;              // 0..3
                float4 v = make_float4(0.f, 0.f, 0.f, 0.f);
                int gm = m0 + row;
                if (gm < M) v = *(const float4*)(A + (size_t)gm * D + k0 + kf * 4);
                As[kf * 4 + 0][row] = v.x;
                As[kf * 4 + 1][row] = v.y;
                As[kf * 4 + 2][row] = v.z;
                As[kf * 4 + 3][row] = v.w;
            }
            // B tile: 16 rows x 64 cols
#pragma unroll
            for (int l = 0; l < 2; l++) {
                int q = tid + l * 128;
                int row = q >> 4;            // 0..15
                int cf = q & 15;             // 0..15
                float4 v = *(const float4*)(B + (size_t)(k0 + row) * D + n0 + cf * 4);
                Bs[row][cf * 4 + 0] = v.x;
                Bs[row][cf * 4 + 1] = v.y;
                Bs[row][cf * 4 + 2] = v.z;
                Bs[row][cf * 4 + 3] = v.w;
            }
            __syncthreads();
#pragma unroll
            for (int k = 0; k < 16; k++) {
                float a[4], b[8];
#pragma unroll
                for (int r = 0; r < 4; r++) a[r] = As[k][tm + r];
#pragma unroll
                for (int c = 0; c < 8; c++) b[c] = Bs[k][tn + c];
#pragma unroll
                for (int r = 0; r < 4; r++)
#pragma unroll
                    for (int c = 0; c < 8; c++)
                        acc[r][c] = fmaf(a[r], b[c], acc[r][c]);
            }
            __syncthreads();
        }
    }

#pragma unroll
    for (int r = 0; r < 4; r++) {
        int gm = m0 + tm + r;
        if (gm >= M) continue;
#pragma unroll
        for (int c = 0; c < 8; c++)
            acc[r][c] = fmaxf(acc[r][c] + bias[n0 + tn + c], 0.f);
        float4 o0 = make_float4(acc[r][0], acc[r][1], acc[r][2], acc[r][3]);
        float4 o1 = make_float4(acc[r][4], acc[r][5], acc[r][6], acc[r][7]);
        *(float4*)(C + (size_t)gm * D + n0 + tn) = o0;
        *(float4*)(C + (size_t)gm * D + n0 + tn + 4) = o1;
    }
}

// ---------------- launch ------------------------------------------------------
extern "C" void kernel_launch(void* const* d_in, const int* in_sizes, int n_in,
                              void* d_out, int out_size) {
    const int* x1    = (const int*)d_in[0];
    const int* ei1   = (const int*)d_in[1];
    const int* batch = (const int*)d_in[2];
    const int* x2ids = (const int*)d_in[3];
    const int* ei2   = (const int*)d_in[4];
    const float* emb1  = (const float*)d_in[5];
    const float* emb2  = (const float*)d_in[6];
    const float* Wl1   = (const float*)d_in[7];
    const float* bl1   = (const float*)d_in[8];
    const float* Wr1   = (const float*)d_in[9];
    const float* lin1W = (const float*)d_in[10];
    const float* lin1b = (const float*)d_in[11];
    const float* Wl2   = (const float*)d_in[12];
    const float* bl2   = (const float*)d_in[13];
    const float* Wr2   = (const float*)d_in[14];
    const float* Wx2   = (const float*)d_in[15];

    const int* src1 = ei1;
    const int* dst1 = ei1 + E1C;
    const int* src2 = ei2;
    const int* dst2 = ei2 + E2C;

    float *x, *y, *agg, *cnt1, *gmax, *gsum, *cntb, *cnt2, *xdrug, *x2a, *x2b, *agg2;
    cudaGetSymbolAddress((void**)&x, g_x);
    cudaGetSymbolAddress((void**)&y, g_y);
    cudaGetSymbolAddress((void**)&agg, g_agg);
    cudaGetSymbolAddress((void**)&cnt1, g_cnt1);
    cudaGetSymbolAddress((void**)&gmax, g_gmax);
    cudaGetSymbolAddress((void**)&gsum, g_gsum);
    cudaGetSymbolAddress((void**)&cntb, g_cntb);
    cudaGetSymbolAddress((void**)&cnt2, g_cnt2);
    cudaGetSymbolAddress((void**)&xdrug, g_xdrug);
    cudaGetSymbolAddress((void**)&x2a, g_x2a);
    cudaGetSymbolAddress((void**)&x2b, g_x2b);
    cudaGetSymbolAddress((void**)&agg2, g_agg2);

    cudaStream_t s = 0;

    // ---- degree counts + reciprocals (structure-only, shared across layers) ----
    cudaMemsetAsync(cnt1, 0, N1C * sizeof(float), s);
    cudaMemsetAsync(cnt2, 0, NDRUG * sizeof(float), s);
    cudaMemsetAsync(cntb, 0, NDRUG * sizeof(float), s);
    count_dst<<<(E1C + 255) / 256, 256, 0, s>>>(dst1, cnt1, E1C);
    count_dst<<<(E2C + 255) / 256, 256, 0, s>>>(dst2, cnt2, E2C);
    count_dst<<<(N1C + 255) / 256, 256, 0, s>>>(batch, cntb, N1C);
    recip_clamp<<<(N1C + 255) / 256, 256, 0, s>>>(cnt1, N1C);
    recip_clamp<<<(NDRUG + 255) / 256, 256, 0, s>>>(cnt2, NDRUG);
    recip_clamp<<<(NDRUG + 255) / 256, 256, 0, s>>>(cntb, NDRUG);

    // ---- level 1 ----
    gather_rows<<<((size_t)N1C * 64 + 255) / 256, 256, 0, s>>>(emb1, x1, x, N1C);

    float* xin = x;
    float* xout = y;
    for (int i = 0; i < 3; i++) {
        cudaMemsetAsync(agg, 0, (size_t)N1C * D * sizeof(float), s);
        edge_scatter<<<((size_t)E1C * 64) / 256, 256, 0, s>>>(xin, src1, dst1, agg, E1C);
        scale_rows<<<((size_t)N1C * 64 + 255) / 256, 256, 0, s>>>(agg, cnt1, N1C);
        gemm3<<<dim3(4, (N1C + 63) / 64), 128, 0, s>>>(
            agg, Wl1 + (size_t)i * DD,
            xin, Wr1 + (size_t)i * DD,
            nullptr, nullptr,
            bl1 + (size_t)i * D, xout, N1C);
        float* t = xin; xin = xout; xout = t;
    }

    // ---- pooling + lin1 ----
    cudaMemsetAsync(gmax, 0, (size_t)NDRUG * D * sizeof(float), s);
    cudaMemsetAsync(gsum, 0, (size_t)NDRUG * D * sizeof(float), s);
    pool_kernel<<<((size_t)N1C * 64 + 255) / 256, 256, 0, s>>>(xin, batch, gmax, gsum, N1C);
    scale_rows<<<((size_t)NDRUG * 64 + 255) / 256, 256, 0, s>>>(gsum, cntb, NDRUG);
    gemm3<<<dim3(4, NDRUG / 64), 128, 0, s>>>(
        gmax, lin1W,
        gsum, lin1W + (size_t)DD,
        nullptr, nullptr,
        lin1b, xdrug, NDRUG);

    // ---- level 2 ----
    gather2_rows<<<((size_t)NDRUG * 64 + 255) / 256, 256, 0, s>>>(xdrug, emb2, x2ids, x2a);
    float* x2in = x2a;
    for (int i = 0; i < 2; i++) {
        cudaMemsetAsync(agg2, 0, (size_t)NDRUG * D * sizeof(float), s);
        edge_scatter<<<((size_t)E2C * 64) / 256, 256, 0, s>>>(x2in, src2, dst2, agg2, E2C);
        scale_rows<<<((size_t)NDRUG * 64 + 255) / 256, 256, 0, s>>>(agg2, cnt2, NDRUG);
        float* outp = (i == 1) ? (float*)d_out : x2b;
        gemm3<<<dim3(4, NDRUG / 64), 128, 0, s>>>(
            agg2, Wl2 + (size_t)i * DD,
            x2in, Wr2 + (size_t)i * DD,
            xdrug, Wx2 + (size_t)i * DD,
            bl2 + (size_t)i * D, outp, NDRUG);
        x2in = x2b;
    }
}

// round 2
// speedup vs baseline: 2.3475x; 2.3475x over previous
#include <cuda_runtime.h>
#include <cstdint>

#define D      256
#define N1C    50000
#define E1C    800000
#define NDRUG  4096
#define E2C    131072
#define DD     (D*D)

// ---------------- scratch (device globals; no allocation allowed) -------------
__device__ float g_x[(size_t)N1C * D];
__device__ float g_y[(size_t)N1C * D];
__device__ float g_agg[(size_t)N1C * D];
__device__ float g_gmax[NDRUG * D];
__device__ float g_gmean[NDRUG * D];
__device__ float g_xdrug[NDRUG * D];
__device__ float g_x2a[NDRUG * D];
__device__ float g_x2b[NDRUG * D];
__device__ float g_agg2[NDRUG * D];

__device__ int g_cnt1i[N1C];
__device__ int g_base1[N1C + 1];
__device__ int g_cur1[N1C];
__device__ int g_csr1[E1C];

__device__ int g_cnt2i[NDRUG];
__device__ int g_base2[NDRUG + 1];
__device__ int g_cur2[NDRUG];
__device__ int g_csr2[E2C];

__device__ int g_bounds[NDRUG + 1];

// ---------------- small kernels ----------------------------------------------

__global__ void gather_rows(const float* __restrict__ emb, const int* __restrict__ ids,
                            float* __restrict__ out, int n) {
    int t = blockIdx.x * blockDim.x + threadIdx.x;
    int i = t >> 6, c = t & 63;
    if (i >= n) return;
    float4 v = ((const float4*)(emb + (size_t)ids[i] * D))[c];
    ((float4*)(out + (size_t)i * D))[c] = v;
}

__global__ void gather2_rows(const float* __restrict__ xdrug, const float* __restrict__ emb2,
                             const int* __restrict__ ids, float* __restrict__ out) {
    int t = blockIdx.x * blockDim.x + threadIdx.x;
    int i = t >> 6, c = t & 63;
    if (i >= NDRUG) return;
    int id = ids[i];
    const float* src = (id < NDRUG) ? (xdrug + (size_t)id * D) : (emb2 + (size_t)id * D);
    ((float4*)(out + (size_t)i * D))[c] = ((const float4*)src)[c];
}

__global__ void count_int(const int* __restrict__ dst, int* __restrict__ cnt, int n) {
    int e = blockIdx.x * blockDim.x + threadIdx.x;
    if (e < n) atomicAdd(&cnt[dst[e]], 1);
}

// single-block exclusive scan; base has n+1 entries, base[n] = total
__global__ void __launch_bounds__(1024) exscan(const int* __restrict__ cnt,
                                               int* __restrict__ base, int n) {
    __shared__ int sh[1024];
    __shared__ int s_carry;
    if (threadIdx.x == 0) s_carry = 0;
    __syncthreads();
    for (int start = 0; start < n; start += 1024) {
        int i = start + threadIdx.x;
        int v = (i < n) ? cnt[i] : 0;
        sh[threadIdx.x] = v;
        __syncthreads();
#pragma unroll
        for (int off = 1; off < 1024; off <<= 1) {
            int t = (threadIdx.x >= off) ? sh[threadIdx.x - off] : 0;
            __syncthreads();
            sh[threadIdx.x] += t;
            __syncthreads();
        }
        if (i < n) base[i] = s_carry + sh[threadIdx.x] - v;
        __syncthreads();
        if (threadIdx.x == 1023) s_carry += sh[1023];
        __syncthreads();
    }
    if (threadIdx.x == 0) base[n] = s_carry;
}

__global__ void fill_csr(const int* __restrict__ src, const int* __restrict__ dst,
                         int* __restrict__ cursor, int* __restrict__ csr, int E) {
    int e = blockIdx.x * blockDim.x + threadIdx.x;
    if (e >= E) return;
    int p = atomicAdd(&cursor[dst[e]], 1);
    csr[p] = src[e];
}

// warp-per-node mean aggregation over CSR (no atomics). 8 warps / block.
__global__ void __launch_bounds__(256) aggregate(
    const float* __restrict__ x, const int* __restrict__ csr,
    const int* __restrict__ base, float* __restrict__ agg, int n) {
    int node = blockIdx.x * 8 + (threadIdx.x >> 5);
    int lane = threadIdx.x & 31;
    if (node >= n) return;
    int lo = base[node], hi = base[node + 1];
    float4 a0 = make_float4(0.f, 0.f, 0.f, 0.f);
    float4 a1 = make_float4(0.f, 0.f, 0.f, 0.f);
    for (int j = lo; j < hi; j++) {
        int s = csr[j];
        const float4* row = (const float4*)(x + (size_t)s * D);
        float4 v0 = row[lane];
        float4 v1 = row[lane + 32];
        a0.x += v0.x; a0.y += v0.y; a0.z += v0.z; a0.w += v0.w;
        a1.x += v1.x; a1.y += v1.y; a1.z += v1.z; a1.w += v1.w;
    }
    float r = 1.f / fmaxf((float)(hi - lo), 1.f);
    a0.x *= r; a0.y *= r; a0.z *= r; a0.w *= r;
    a1.x *= r; a1.y *= r; a1.z *= r; a1.w *= r;
    float4* out = (float4*)(agg + (size_t)node * D);
    out[lane] = a0;
    out[lane + 32] = a1;
}

// lower_bound(batch, b) for b in [0, nseg]
__global__ void seg_bounds(const int* __restrict__ batch, int* __restrict__ bounds,
                           int n, int nseg) {
    int b = blockIdx.x * blockDim.x + threadIdx.x;
    if (b > nseg) return;
    int lo = 0, hi = n;
    while (lo < hi) {
        int mid = (lo + hi) >> 1;
        if (batch[mid] < b) lo = mid + 1; else hi = mid;
    }
    bounds[b] = lo;
}

// warp-per-drug max + mean pooling over a contiguous row range (batch is sorted)
__global__ void __launch_bounds__(256) pool2(
    const float* __restrict__ x, const int* __restrict__ bounds,
    float* __restrict__ gmax, float* __restrict__ gmean) {
    int drug = blockIdx.x * 8 + (threadIdx.x >> 5);
    int lane = threadIdx.x & 31;
    if (drug >= NDRUG) return;
    int lo = bounds[drug], hi = bounds[drug + 1];
    float4 m0 = make_float4(0.f, 0.f, 0.f, 0.f);
    float4 m1 = make_float4(0.f, 0.f, 0.f, 0.f);
    float4 s0 = make_float4(0.f, 0.f, 0.f, 0.f);
    float4 s1 = make_float4(0.f, 0.f, 0.f, 0.f);
    for (int i = lo; i < hi; i++) {
        const float4* row = (const float4*)(x + (size_t)i * D);
        float4 v0 = row[lane];
        float4 v1 = row[lane + 32];
        m0.x = fmaxf(m0.x, v0.x); m0.y = fmaxf(m0.y, v0.y);
        m0.z = fmaxf(m0.z, v0.z); m0.w = fmaxf(m0.w, v0.w);
        m1.x = fmaxf(m1.x, v1.x); m1.y = fmaxf(m1.y, v1.y);
        m1.z = fmaxf(m1.z, v1.z); m1.w = fmaxf(m1.w, v1.w);
        s0.x += v0.x; s0.y += v0.y; s0.z += v0.z; s0.w += v0.w;
        s1.x += v1.x; s1.y += v1.y; s1.z += v1.z; s1.w += v1.w;
    }
    float r = 1.f / fmaxf((float)(hi - lo), 1.f);
    s0.x *= r; s0.y *= r; s0.z *= r; s0.w *= r;
    s1.x *= r; s1.y *= r; s1.z *= r; s1.w *= r;
    float4* om = (float4*)(gmax + (size_t)drug * D);
    float4* os = (float4*)(gmean + (size_t)drug * D);
    om[lane] = m0; om[lane + 32] = m1;
    os[lane] = s0; os[lane + 32] = s1;
}

// ---------------- fused multi-segment GEMM ------------------------------------
// C[M,256] = relu( sum_s A_s[M,256] @ B_s[256,256] + bias ), up to 3 segments.
// BM=128, BN=64, BK=16, 256 threads, 8x4 microtile, all-LDS.128 inner loop.
__global__ void __launch_bounds__(256) gemm3(
    const float* A0, const float* B0,
    const float* A1, const float* B1,
    const float* A2, const float* B2,
    const float* __restrict__ bias,
    float* __restrict__ C, int M) {
    __shared__ float As[16][136];   // [k][m], padded
    __shared__ float Bs[16][64];    // [k][n]
    const int tid = threadIdx.x;
    const int m0 = blockIdx.y * 128;
    const int n0 = blockIdx.x * 64;
    const int tm = (tid >> 4) * 8;   // 0..120
    const int tn = (tid & 15) * 4;   // 0..60

    float acc[8][4];
#pragma unroll
    for (int r = 0; r < 8; r++)
#pragma unroll
        for (int c = 0; c < 4; c++) acc[r][c] = 0.f;

    const float* Aseg[3] = {A0, A1, A2};
    const float* Bseg[3] = {B0, B1, B2};

    for (int sgi = 0; sgi < 3; sgi++) {
        const float* A = Aseg[sgi];
        if (!A) break;
        const float* B = Bseg[sgi];
        for (int k0 = 0; k0 < D; k0 += 16) {
            // A tile: 128 rows x 16 cols -> transposed As[k][m]; 512 float4 loads
#pragma unroll
            for (int l = 0; l < 2; l++) {
                int q = tid + l * 256;        // 0..511
                int row = q >> 2;             // 0..127
                int kf = q & 3;               // 0..3
                float4 v = make_float4(0.f, 0.f, 0.f, 0.f);
                int gm = m0 + row;
                if (gm < M) v = *(const float4*)(A + (size_t)gm * D + k0 + kf * 4);
                As[kf * 4 + 0][row] = v.x;
                As[kf * 4 + 1][row] = v.y;
                As[kf * 4 + 2][row] = v.z;
                As[kf * 4 + 3][row] = v.w;
            }
            // B tile: 16 rows x 64 cols; 256 float4 loads
            {
                int row = tid >> 4;           // 0..15
                int cf = tid & 15;            // 0..15
                float4 v = *(const float4*)(B + (size_t)(k0 + row) * D + n0 + cf * 4);
                *(float4*)&Bs[row][cf * 4] = v;
            }
            __syncthreads();
#pragma unroll
            for (int k = 0; k < 16; k++) {
                float4 a0 = *(const float4*)&As[k][tm];
                float4 a1 = *(const float4*)&As[k][tm + 4];
                float4 b  = *(const float4*)&Bs[k][tn];
                acc[0][0] = fmaf(a0.x, b.x, acc[0][0]);
                acc[0][1] = fmaf(a0.x, b.y, acc[0][1]);
                acc[0][2] = fmaf(a0.x, b.z, acc[0][2]);
                acc[0][3] = fmaf(a0.x, b.w, acc[0][3]);
                acc[1][0] = fmaf(a0.y, b.x, acc[1][0]);
                acc[1][1] = fmaf(a0.y, b.y, acc[1][1]);
                acc[1][2] = fmaf(a0.y, b.z, acc[1][2]);
                acc[1][3] = fmaf(a0.y, b.w, acc[1][3]);
                acc[2][0] = fmaf(a0.z, b.x, acc[2][0]);
                acc[2][1] = fmaf(a0.z, b.y, acc[2][1]);
                acc[2][2] = fmaf(a0.z, b.z, acc[2][2]);
                acc[2][3] = fmaf(a0.z, b.w, acc[2][3]);
                acc[3][0] = fmaf(a0.w, b.x, acc[3][0]);
                acc[3][1] = fmaf(a0.w, b.y, acc[3][1]);
                acc[3][2] = fmaf(a0.w, b.z, acc[3][2]);
                acc[3][3] = fmaf(a0.w, b.w, acc[3][3]);
                acc[4][0] = fmaf(a1.x, b.x, acc[4][0]);
                acc[4][1] = fmaf(a1.x, b.y, acc[4][1]);
                acc[4][2] = fmaf(a1.x, b.z, acc[4][2]);
                acc[4][3] = fmaf(a1.x, b.w, acc[4][3]);
                acc[5][0] = fmaf(a1.y, b.x, acc[5][0]);
                acc[5][1] = fmaf(a1.y, b.y, acc[5][1]);
                acc[5][2] = fmaf(a1.y, b.z, acc[5][2]);
                acc[5][3] = fmaf(a1.y, b.w, acc[5][3]);
                acc[6][0] = fmaf(a1.z, b.x, acc[6][0]);
                acc[6][1] = fmaf(a1.z, b.y, acc[6][1]);
                acc[6][2] = fmaf(a1.z, b.z, acc[6][2]);
                acc[6][3] = fmaf(a1.z, b.w, acc[6][3]);
                acc[7][0] = fmaf(a1.w, b.x, acc[7][0]);
                acc[7][1] = fmaf(a1.w, b.y, acc[7][1]);
                acc[7][2] = fmaf(a1.w, b.z, acc[7][2]);
                acc[7][3] = fmaf(a1.w, b.w, acc[7][3]);
            }
            __syncthreads();
        }
    }

    float4 bb = *(const float4*)(bias + n0 + tn);
#pragma unroll
    for (int r = 0; r < 8; r++) {
        int gm = m0 + tm + r;
        if (gm >= M) continue;
        float4 o;
        o.x = fmaxf(acc[r][0] + bb.x, 0.f);
        o.y = fmaxf(acc[r][1] + bb.y, 0.f);
        o.z = fmaxf(acc[r][2] + bb.z, 0.f);
        o.w = fmaxf(acc[r][3] + bb.w, 0.f);
        *(float4*)(C + (size_t)gm * D + n0 + tn) = o;
    }
}

// ---------------- launch ------------------------------------------------------
extern "C" void kernel_launch(void* const* d_in, const int* in_sizes, int n_in,
                              void* d_out, int out_size) {
    const int* x1    = (const int*)d_in[0];
    const int* ei1   = (const int*)d_in[1];
    const int* batch = (const int*)d_in[2];
    const int* x2ids = (const int*)d_in[3];
    const int* ei2   = (const int*)d_in[4];
    const float* emb1  = (const float*)d_in[5];
    const float* emb2  = (const float*)d_in[6];
    const float* Wl1   = (const float*)d_in[7];
    const float* bl1   = (const float*)d_in[8];
    const float* Wr1   = (const float*)d_in[9];
    const float* lin1W = (const float*)d_in[10];
    const float* lin1b = (const float*)d_in[11];
    const float* Wl2   = (const float*)d_in[12];
    const float* bl2   = (const float*)d_in[13];
    const float* Wr2   = (const float*)d_in[14];
    const float* Wx2   = (const float*)d_in[15];

    const int* src1 = ei1;
    const int* dst1 = ei1 + E1C;
    const int* src2 = ei2;
    const int* dst2 = ei2 + E2C;

    float *x, *y, *agg, *gmax, *gmean, *xdrug, *x2a, *x2b, *agg2;
    int *cnt1i, *base1, *cur1, *csr1, *cnt2i, *base2, *cur2, *csr2, *bounds;
    cudaGetSymbolAddress((void**)&x, g_x);
    cudaGetSymbolAddress((void**)&y, g_y);
    cudaGetSymbolAddress((void**)&agg, g_agg);
    cudaGetSymbolAddress((void**)&gmax, g_gmax);
    cudaGetSymbolAddress((void**)&gmean, g_gmean);
    cudaGetSymbolAddress((void**)&xdrug, g_xdrug);
    cudaGetSymbolAddress((void**)&x2a, g_x2a);
    cudaGetSymbolAddress((void**)&x2b, g_x2b);
    cudaGetSymbolAddress((void**)&agg2, g_agg2);
    cudaGetSymbolAddress((void**)&cnt1i, g_cnt1i);
    cudaGetSymbolAddress((void**)&base1, g_base1);
    cudaGetSymbolAddress((void**)&cur1, g_cur1);
    cudaGetSymbolAddress((void**)&csr1, g_csr1);
    cudaGetSymbolAddress((void**)&cnt2i, g_cnt2i);
    cudaGetSymbolAddress((void**)&base2, g_base2);
    cudaGetSymbolAddress((void**)&cur2, g_cur2);
    cudaGetSymbolAddress((void**)&csr2, g_csr2);
    cudaGetSymbolAddress((void**)&bounds, g_bounds);

    cudaStream_t s = 0;

    // ---- CSR build for both graphs (structure only, once per call) ----
    cudaMemsetAsync(cnt1i, 0, N1C * sizeof(int), s);
    cudaMemsetAsync(cnt2i, 0, NDRUG * sizeof(int), s);
    count_int<<<(E1C + 255) / 256, 256, 0, s>>>(dst1, cnt1i, E1C);
    count_int<<<(E2C + 255) / 256, 256, 0, s>>>(dst2, cnt2i, E2C);
    exscan<<<1, 1024, 0, s>>>(cnt1i, base1, N1C);
    exscan<<<1, 1024, 0, s>>>(cnt2i, base2, NDRUG);
    cudaMemcpyAsync(cur1, base1, N1C * sizeof(int), cudaMemcpyDeviceToDevice, s);
    cudaMemcpyAsync(cur2, base2, NDRUG * sizeof(int), cudaMemcpyDeviceToDevice, s);
    fill_csr<<<(E1C + 255) / 256, 256, 0, s>>>(src1, dst1, cur1, csr1, E1C);
    fill_csr<<<(E2C + 255) / 256, 256, 0, s>>>(src2, dst2, cur2, csr2, E2C);
    seg_bounds<<<(NDRUG + 1 + 255) / 256, 256, 0, s>>>(batch, bounds, N1C, NDRUG);

    // ---- level 1 ----
    gather_rows<<<((size_t)N1C * 64 + 255) / 256, 256, 0, s>>>(emb1, x1, x, N1C);

    float* xin = x;
    float* xout = y;
    for (int i = 0; i < 3; i++) {
        aggregate<<<(N1C + 7) / 8, 256, 0, s>>>(xin, csr1, base1, agg, N1C);
        gemm3<<<dim3(4, (N1C + 127) / 128), 256, 0, s>>>(
            agg, Wl1 + (size_t)i * DD,
            xin, Wr1 + (size_t)i * DD,
            nullptr, nullptr,
            bl1 + (size_t)i * D, xout, N1C);
        float* t = xin; xin = xout; xout = t;
    }

    // ---- pooling + lin1 ----
    pool2<<<NDRUG / 8, 256, 0, s>>>(xin, bounds, gmax, gmean);
    gemm3<<<dim3(4, NDRUG / 128), 256, 0, s>>>(
        gmax, lin1W,
        gmean, lin1W + (size_t)DD,
        nullptr, nullptr,
        lin1b, xdrug, NDRUG);

    // ---- level 2 ----
    gather2_rows<<<((size_t)NDRUG * 64 + 255) / 256, 256, 0, s>>>(xdrug, emb2, x2ids, x2a);
    float* x2in = x2a;
    for (int i = 0; i < 2; i++) {
        aggregate<<<(NDRUG + 7) / 8, 256, 0, s>>>(x2in, csr2, base2, agg2, NDRUG);
        float* outp = (i == 1) ? (float*)d_out : x2b;
        gemm3<<<dim3(4, NDRUG / 128), 256, 0, s>>>(
            agg2, Wl2 + (size_t)i * DD,
            x2in, Wr2 + (size_t)i * DD,
            xdrug, Wx2 + (size_t)i * DD,
            bl2 + (size_t)i * D, outp, NDRUG);
        x2in = x2b;
    }
}

// round 4
// speedup vs baseline: 4.6261x; 1.9706x over previous
#include <cuda_runtime.h>
#include <cstdint>

#define D      256
#define N1C    50000
#define E1C    800000
#define NDRUG  4096
#define E2C    131072
#define DD     (D*D)

// ---------------- scratch (device globals; no allocation allowed) -------------
__device__ float g_x[(size_t)N1C * D];
__device__ float g_y[(size_t)N1C * D];
__device__ float g_agg[(size_t)N1C * D];
__device__ float g_gmax[NDRUG * D];
__device__ float g_gmean[NDRUG * D];
__device__ float g_xdrug[NDRUG * D];
__device__ float g_x2a[NDRUG * D];
__device__ float g_x2b[NDRUG * D];
__device__ float g_agg2[NDRUG * D];
__device__ float g_wt[14 * DD];          // transposed (and tf32-rounded) weights

__device__ int g_cnt1i[N1C];
__device__ int g_base1[N1C + 1];
__device__ int g_cur1[N1C];
__device__ int g_csr1[E1C];

__device__ int g_cnt2i[NDRUG];
__device__ int g_base2[NDRUG + 1];
__device__ int g_cur2[NDRUG];
__device__ int g_csr2[E2C];

__device__ int g_bounds[NDRUG + 1];

// ---------------- helpers -----------------------------------------------------
__device__ __forceinline__ uint32_t f2tf(float x) {   // round-to-nearest tf32 bits
    uint32_t u;
    asm("cvt.rna.tf32.f32 %0, %1;" : "=r"(u) : "f"(x));
    return u;
}

__device__ __forceinline__ void mma_tf32(float* c, const uint32_t* a, const uint32_t* b) {
    asm volatile(
        "mma.sync.aligned.m16n8k8.row.col.f32.tf32.tf32.f32 "
        "{%0,%1,%2,%3}, {%4,%5,%6,%7}, {%8,%9}, {%0,%1,%2,%3};"
        : "+f"(c[0]), "+f"(c[1]), "+f"(c[2]), "+f"(c[3])
        : "r"(a[0]), "r"(a[1]), "r"(a[2]), "r"(a[3]), "r"(b[0]), "r"(b[1]));
}

// ---------------- tensor-core GEMM (mma.sync tf32) -----------------------------
// C[M,256] = relu( sum_s A_s[M,256] @ B_s^T + bias ),  B_s given as [256,256]
// row-major [N][K], pre-transposed and tf32-rounded.
// BM=128, BN=128, BK=32; 256 threads; warp grid 2(M) x 4(N); warp tile 64x32.
#define SMSTRIDE 36
#define TILE_F   (128 * SMSTRIDE)                 // floats per tile buffer
#define GEMM_SMEM (4 * TILE_F * 4)                // As[2] + Bs[2], bytes

__global__ void __launch_bounds__(256) gemm_tc(
    const float* A0, const float* B0,
    const float* A1, const float* B1,
    const float* A2, const float* B2,
    const float* __restrict__ bias,
    float* __restrict__ C, int M, int nseg) {
    extern __shared__ float sm[];
    float* As = sm;                    // [2][128][36]
    float* Bs = sm + 2 * TILE_F;       // [2][128][36]

    const int tid = threadIdx.x;
    const int wid = tid >> 5;
    const int lane = tid & 31;
    const int g = lane >> 2;           // 0..7
    const int tq = lane & 3;           // 0..3
    const int wm = (wid >> 2) * 64;    // 0 / 64
    const int wn = (wid & 3) * 32;     // 0 / 32 / 64 / 96
    const int m0 = blockIdx.y * 128;
    const int n0 = blockIdx.x * 128;

    // staging coords: 4 float4 per thread per tile
    int srow[4], sf4[4];
#pragma unroll
    for (int it = 0; it < 4; it++) {
        int idx = tid + it * 256;
        srow[it] = idx >> 3;
        sf4[it] = idx & 7;
    }

    float acc[4][4][4];
#pragma unroll
    for (int mt = 0; mt < 4; mt++)
#pragma unroll
        for (int nt = 0; nt < 4; nt++)
#pragma unroll
            for (int q = 0; q < 4; q++) acc[mt][nt][q] = 0.f;

    const float* Aseg[3] = { A0, A1, A2 };
    const float* Bseg[3] = { B0, B1, B2 };
    const int total = nseg * 8;

    float4 av[4], bv[4];

    // prologue: load tile 0
    {
        const float* A = Aseg[0];
        const float* B = Bseg[0];
#pragma unroll
        for (int it = 0; it < 4; it++) {
            int gm = m0 + srow[it];
            av[it] = (gm < M) ? *(const float4*)(A + (size_t)gm * D + sf4[it] * 4)
                              : make_float4(0.f, 0.f, 0.f, 0.f);
            bv[it] = *(const float4*)(B + (size_t)(n0 + srow[it]) * D + sf4[it] * 4);
        }
#pragma unroll
        for (int it = 0; it < 4; it++) {
            uint4 u;
            u.x = f2tf(av[it].x); u.y = f2tf(av[it].y);
            u.z = f2tf(av[it].z); u.w = f2tf(av[it].w);
            *(uint4*)(As + srow[it] * SMSTRIDE + sf4[it] * 4) = u;
            *(float4*)(Bs + srow[it] * SMSTRIDE + sf4[it] * 4) = bv[it];
        }
    }
    __syncthreads();

    for (int t = 0; t < total; t++) {
        const int buf = t & 1;
        // prefetch next tile into registers
        if (t + 1 < total) {
            const float* A = Aseg[(t + 1) >> 3];
            const float* B = Bseg[(t + 1) >> 3];
            const int kc = (t + 1) & 7;
#pragma unroll
            for (int it = 0; it < 4; it++) {
                int gm = m0 + srow[it];
                av[it] = (gm < M) ? *(const float4*)(A + (size_t)gm * D + kc * 32 + sf4[it] * 4)
                                  : make_float4(0.f, 0.f, 0.f, 0.f);
                bv[it] = *(const float4*)(B + (size_t)(n0 + srow[it]) * D + kc * 32 + sf4[it] * 4);
            }
        }

        // compute current tile
        const float* Ab = As + buf * TILE_F;
        const float* Bb = Bs + buf * TILE_F;
#pragma unroll
        for (int k8 = 0; k8 < 4; k8++) {
            const int kb = k8 * 8;
            uint32_t af[4][4], bf[4][2];
#pragma unroll
            for (int mt = 0; mt < 4; mt++) {
                int r = wm + mt * 16 + g;
                af[mt][0] = __float_as_uint(Ab[r * SMSTRIDE + kb + tq]);
                af[mt][1] = __float_as_uint(Ab[(r + 8) * SMSTRIDE + kb + tq]);
                af[mt][2] = __float_as_uint(Ab[r * SMSTRIDE + kb + tq + 4]);
                af[mt][3] = __float_as_uint(Ab[(r + 8) * SMSTRIDE + kb + tq + 4]);
            }
#pragma unroll
            for (int nt = 0; nt < 4; nt++) {
                int n = wn + nt * 8 + g;
                bf[nt][0] = __float_as_uint(Bb[n * SMSTRIDE + kb + tq]);
                bf[nt][1] = __float_as_uint(Bb[n * SMSTRIDE + kb + tq + 4]);
            }
#pragma unroll
            for (int mt = 0; mt < 4; mt++)
#pragma unroll
                for (int nt = 0; nt < 4; nt++)
                    mma_tf32(acc[mt][nt], af[mt], bf[nt]);
        }

        // store prefetched tile into the other buffer
        if (t + 1 < total) {
            __syncthreads();
            float* An = As + (buf ^ 1) * TILE_F;
            float* Bn = Bs + (buf ^ 1) * TILE_F;
#pragma unroll
            for (int it = 0; it < 4; it++) {
                uint4 u;
                u.x = f2tf(av[it].x); u.y = f2tf(av[it].y);
                u.z = f2tf(av[it].z); u.w = f2tf(av[it].w);
                *(uint4*)(An + srow[it] * SMSTRIDE + sf4[it] * 4) = u;
                *(float4*)(Bn + srow[it] * SMSTRIDE + sf4[it] * 4) = bv[it];
            }
            __syncthreads();
        }
    }

    // epilogue: bias + relu, float2 stores
#pragma unroll
    for (int mt = 0; mt < 4; mt++) {
        int mlo = m0 + wm + mt * 16 + g;
#pragma unroll
        for (int nt = 0; nt < 4; nt++) {
            int n = n0 + wn + nt * 8 + tq * 2;
            float b0 = bias[n], b1 = bias[n + 1];
            if (mlo < M) {
                float2 o;
                o.x = fmaxf(acc[mt][nt][0] + b0, 0.f);
                o.y = fmaxf(acc[mt][nt][1] + b1, 0.f);
                *(float2*)(C + (size_t)mlo * D + n) = o;
            }
            if (mlo + 8 < M) {
                float2 o;
                o.x = fmaxf(acc[mt][nt][2] + b0, 0.f);
                o.y = fmaxf(acc[mt][nt][3] + b1, 0.f);
                *(float2*)(C + (size_t)(mlo + 8) * D + n) = o;
            }
        }
    }
}

// ---------------- weight transpose (+ tf32 rounding) --------------------------
struct WTP { const float* src[14]; float* dst[14]; };

__global__ void transpose_tf32(WTP p) {
    __shared__ float t[32][33];
    const float* src = p.src[blockIdx.z];
    float* dst = p.dst[blockIdx.z];
    int x = blockIdx.x * 32 + threadIdx.x;
    int y0 = blockIdx.y * 32 + threadIdx.y;
#pragma unroll
    for (int i = 0; i < 32; i += 8)
        t[threadIdx.y + i][threadIdx.x] = src[(size_t)(y0 + i) * D + x];
    __syncthreads();
    int x2 = blockIdx.y * 32 + threadIdx.x;
    int y2 = blockIdx.x * 32 + threadIdx.y;
#pragma unroll
    for (int i = 0; i < 32; i += 8) {
        uint32_t u = f2tf(t[threadIdx.x][threadIdx.y + i]);
        dst[(size_t)(y2 + i) * D + x2] = __uint_as_float(u);
    }
}

// ---------------- small kernels ------------------------------------------------
__global__ void gather_rows(const float* __restrict__ emb, const int* __restrict__ ids,
                            float* __restrict__ out, int n) {
    int t = blockIdx.x * blockDim.x + threadIdx.x;
    int i = t >> 6, c = t & 63;
    if (i >= n) return;
    float4 v = ((const float4*)(emb + (size_t)ids[i] * D))[c];
    ((float4*)(out + (size_t)i * D))[c] = v;
}

__global__ void gather2_rows(const float* __restrict__ xdrug, const float* __restrict__ emb2,
                             const int* __restrict__ ids, float* __restrict__ out) {
    int t = blockIdx.x * blockDim.x + threadIdx.x;
    int i = t >> 6, c = t & 63;
    if (i >= NDRUG) return;
    int id = ids[i];
    const float* src = (id < NDRUG) ? (xdrug + (size_t)id * D) : (emb2 + (size_t)id * D);
    ((float4*)(out + (size_t)i * D))[c] = ((const float4*)src)[c];
}

__global__ void count_int(const int* __restrict__ dst, int* __restrict__ cnt, int n) {
    int e = blockIdx.x * blockDim.x + threadIdx.x;
    if (e < n) atomicAdd(&cnt[dst[e]], 1);
}

__global__ void __launch_bounds__(1024) exscan(const int* __restrict__ cnt,
                                               int* __restrict__ base, int n) {
    __shared__ int sh[1024];
    __shared__ int s_carry;
    if (threadIdx.x == 0) s_carry = 0;
    __syncthreads();
    for (int start = 0; start < n; start += 1024) {
        int i = start + threadIdx.x;
        int v = (i < n) ? cnt[i] : 0;
        sh[threadIdx.x] = v;
        __syncthreads();
#pragma unroll
        for (int off = 1; off < 1024; off <<= 1) {
            int t = (threadIdx.x >= off) ? sh[threadIdx.x - off] : 0;
            __syncthreads();
            sh[threadIdx.x] += t;
            __syncthreads();
        }
        if (i < n) base[i] = s_carry + sh[threadIdx.x] - v;
        __syncthreads();
        if (threadIdx.x == 1023) s_carry += sh[1023];
        __syncthreads();
    }
    if (threadIdx.x == 0) base[n] = s_carry;
}

__global__ void fill_csr(const int* __restrict__ src, const int* __restrict__ dst,
                         int* __restrict__ cursor, int* __restrict__ csr, int E) {
    int e = blockIdx.x * blockDim.x + threadIdx.x;
    if (e >= E) return;
    int p = atomicAdd(&cursor[dst[e]], 1);
    csr[p] = src[e];
}

__global__ void __launch_bounds__(256) aggregate(
    const float* __restrict__ x, const int* __restrict__ csr,
    const int* __restrict__ base, float* __restrict__ agg, int n) {
    int node = blockIdx.x * 8 + (threadIdx.x >> 5);
    int lane = threadIdx.x & 31;
    if (node >= n) return;
    int lo = base[node], hi = base[node + 1];
    float4 a0 = make_float4(0.f, 0.f, 0.f, 0.f);
    float4 a1 = make_float4(0.f, 0.f, 0.f, 0.f);
    for (int j = lo; j < hi; j++) {
        int s = csr[j];
        const float4* row = (const float4*)(x + (size_t)s * D);
        float4 v0 = row[lane];
        float4 v1 = row[lane + 32];
        a0.x += v0.x; a0.y += v0.y; a0.z += v0.z; a0.w += v0.w;
        a1.x += v1.x; a1.y += v1.y; a1.z += v1.z; a1.w += v1.w;
    }
    float r = 1.f / fmaxf((float)(hi - lo), 1.f);
    a0.x *= r; a0.y *= r; a0.z *= r; a0.w *= r;
    a1.x *= r; a1.y *= r; a1.z *= r; a1.w *= r;
    float4* out = (float4*)(agg + (size_t)node * D);
    out[lane] = a0;
    out[lane + 32] = a1;
}

__global__ void seg_bounds(const int* __restrict__ batch, int* __restrict__ bounds,
                           int n, int nseg) {
    int b = blockIdx.x * blockDim.x + threadIdx.x;
    if (b > nseg) return;
    int lo = 0, hi = n;
    while (lo < hi) {
        int mid = (lo + hi) >> 1;
        if (batch[mid] < b) lo = mid + 1; else hi = mid;
    }
    bounds[b] = lo;
}

__global__ void __launch_bounds__(256) pool2(
    const float* __restrict__ x, const int* __restrict__ bounds,
    float* __restrict__ gmax, float* __restrict__ gmean) {
    int drug = blockIdx.x * 8 + (threadIdx.x >> 5);
    int lane = threadIdx.x & 31;
    if (drug >= NDRUG) return;
    int lo = bounds[drug], hi = bounds[drug + 1];
    float4 m0 = make_float4(0.f, 0.f, 0.f, 0.f);
    float4 m1 = make_float4(0.f, 0.f, 0.f, 0.f);
    float4 s0 = make_float4(0.f, 0.f, 0.f, 0.f);
    float4 s1 = make_float4(0.f, 0.f, 0.f, 0.f);
    for (int i = lo; i < hi; i++) {
        const float4* row = (const float4*)(x + (size_t)i * D);
        float4 v0 = row[lane];
        float4 v1 = row[lane + 32];
        m0.x = fmaxf(m0.x, v0.x); m0.y = fmaxf(m0.y, v0.y);
        m0.z = fmaxf(m0.z, v0.z); m0.w = fmaxf(m0.w, v0.w);
        m1.x = fmaxf(m1.x, v1.x); m1.y = fmaxf(m1.y, v1.y);
        m1.z = fmaxf(m1.z, v1.z); m1.w = fmaxf(m1.w, v1.w);
        s0.x += v0.x; s0.y += v0.y; s0.z += v0.z; s0.w += v0.w;
        s1.x += v1.x; s1.y += v1.y; s1.z += v1.z; s1.w += v1.w;
    }
    float r = 1.f / fmaxf((float)(hi - lo), 1.f);
    s0.x *= r; s0.y *= r; s0.z *= r; s0.w *= r;
    s1.x *= r; s1.y *= r; s1.z *= r; s1.w *= r;
    float4* om = (float4*)(gmax + (size_t)drug * D);
    float4* os = (float4*)(gmean + (size_t)drug * D);
    om[lane] = m0; om[lane + 32] = m1;
    os[lane] = s0; os[lane + 32] = s1;
}

// ---------------- launch ------------------------------------------------------
extern "C" void kernel_launch(void* const* d_in, const int* in_sizes, int n_in,
                              void* d_out, int out_size) {
    const int* x1    = (const int*)d_in[0];
    const int* ei1   = (const int*)d_in[1];
    const int* batch = (const int*)d_in[2];
    const int* x2ids = (const int*)d_in[3];
    const int* ei2   = (const int*)d_in[4];
    const float* emb1  = (const float*)d_in[5];
    const float* emb2  = (const float*)d_in[6];
    const float* Wl1   = (const float*)d_in[7];
    const float* bl1   = (const float*)d_in[8];
    const float* Wr1   = (const float*)d_in[9];
    const float* lin1W = (const float*)d_in[10];
    const float* lin1b = (const float*)d_in[11];
    const float* Wl2   = (const float*)d_in[12];
    const float* bl2   = (const float*)d_in[13];
    const float* Wr2   = (const float*)d_in[14];
    const float* Wx2   = (const float*)d_in[15];

    const int* src1 = ei1;
    const int* dst1 = ei1 + E1C;
    const int* src2 = ei2;
    const int* dst2 = ei2 + E2C;

    float *x, *y, *agg, *gmax, *gmean, *xdrug, *x2a, *x2b, *agg2, *wt;
    int *cnt1i, *base1, *cur1, *csr1, *cnt2i, *base2, *cur2, *csr2, *bounds;
    cudaGetSymbolAddress((void**)&x, g_x);
    cudaGetSymbolAddress((void**)&y, g_y);
    cudaGetSymbolAddress((void**)&agg, g_agg);
    cudaGetSymbolAddress((void**)&gmax, g_gmax);
    cudaGetSymbolAddress((void**)&gmean, g_gmean);
    cudaGetSymbolAddress((void**)&xdrug, g_xdrug);
    cudaGetSymbolAddress((void**)&x2a, g_x2a);
    cudaGetSymbolAddress((void**)&x2b, g_x2b);
    cudaGetSymbolAddress((void**)&agg2, g_agg2);
    cudaGetSymbolAddress((void**)&wt, g_wt);
    cudaGetSymbolAddress((void**)&cnt1i, g_cnt1i);
    cudaGetSymbolAddress((void**)&base1, g_base1);
    cudaGetSymbolAddress((void**)&cur1, g_cur1);
    cudaGetSymbolAddress((void**)&csr1, g_csr1);
    cudaGetSymbolAddress((void**)&cnt2i, g_cnt2i);
    cudaGetSymbolAddress((void**)&base2, g_base2);
    cudaGetSymbolAddress((void**)&cur2, g_cur2);
    cudaGetSymbolAddress((void**)&csr2, g_csr2);
    cudaGetSymbolAddress((void**)&bounds, g_bounds);

    cudaFuncSetAttribute(gemm_tc, cudaFuncAttributeMaxDynamicSharedMemorySize, GEMM_SMEM);

    cudaStream_t s = 0;

    // ---- weight transposes (+ tf32 rounding), once per call ----
    WTP wp;
    for (int i = 0; i < 3; i++) { wp.src[i]     = Wl1 + (size_t)i * DD; }
    for (int i = 0; i < 3; i++) { wp.src[3 + i] = Wr1 + (size_t)i * DD; }
    wp.src[6] = lin1W;                 // gmax part  [256,256]
    wp.src[7] = lin1W + (size_t)DD;    // gmean part [256,256]
    for (int i = 0; i < 2; i++) { wp.src[8 + i]  = Wl2 + (size_t)i * DD; }
    for (int i = 0; i < 2; i++) { wp.src[10 + i] = Wr2 + (size_t)i * DD; }
    for (int i = 0; i < 2; i++) { wp.src[12 + i] = Wx2 + (size_t)i * DD; }
    for (int i = 0; i < 14; i++) wp.dst[i] = wt + (size_t)i * DD;
    transpose_tf32<<<dim3(8, 8, 14), dim3(32, 8), 0, s>>>(wp);

    // ---- CSR build for both graphs ----
    cudaMemsetAsync(cnt1i, 0, N1C * sizeof(int), s);
    cudaMemsetAsync(cnt2i, 0, NDRUG * sizeof(int), s);
    count_int<<<(E1C + 255) / 256, 256, 0, s>>>(dst1, cnt1i, E1C);
    count_int<<<(E2C + 255) / 256, 256, 0, s>>>(dst2, cnt2i, E2C);
    exscan<<<1, 1024, 0, s>>>(cnt1i, base1, N1C);
    exscan<<<1, 1024, 0, s>>>(cnt2i, base2, NDRUG);
    cudaMemcpyAsync(cur1, base1, N1C * sizeof(int), cudaMemcpyDeviceToDevice, s);
    cudaMemcpyAsync(cur2, base2, NDRUG * sizeof(int), cudaMemcpyDeviceToDevice, s);
    fill_csr<<<(E1C + 255) / 256, 256, 0, s>>>(src1, dst1, cur1, csr1, E1C);
    fill_csr<<<(E2C + 255) / 256, 256, 0, s>>>(src2, dst2, cur2, csr2, E2C);
    seg_bounds<<<(NDRUG + 1 + 255) / 256, 256, 0, s>>>(batch, bounds, N1C, NDRUG);

    // ---- level 1 ----
    gather_rows<<<((size_t)N1C * 64 + 255) / 256, 256, 0, s>>>(emb1, x1, x, N1C);

    float* xin = x;
    float* xout = y;
    const dim3 gg1(2, (N1C + 127) / 128);
    for (int i = 0; i < 3; i++) {
        aggregate<<<(N1C + 7) / 8, 256, 0, s>>>(xin, csr1, base1, agg, N1C);
        gemm_tc<<<gg1, 256, GEMM_SMEM, s>>>(
            agg, wt + (size_t)i * DD,
            xin, wt + (size_t)(3 + i) * DD,
            nullptr, nullptr,
            bl1 + (size_t)i * D, xout, N1C, 2);
        float* t = xin; xin = xout; xout = t;
    }

    // ---- pooling + lin1 ----
    pool2<<<NDRUG / 8, 256, 0, s>>>(xin, bounds, gmax, gmean);
    gemm_tc<<<dim3(2, NDRUG / 128), 256, GEMM_SMEM, s>>>(
        gmax, wt + (size_t)6 * DD,
        gmean, wt + (size_t)7 * DD,
        nullptr, nullptr,
        lin1b, xdrug, NDRUG, 2);

    // ---- level 2 ----
    gather2_rows<<<((size_t)NDRUG * 64 + 255) / 256, 256, 0, s>>>(xdrug, emb2, x2ids, x2a);
    float* x2in = x2a;
    for (int i = 0; i < 2; i++) {
        aggregate<<<(NDRUG + 7) / 8, 256, 0, s>>>(x2in, csr2, base2, agg2, NDRUG);
        float* outp = (i == 1) ? (float*)d_out : x2b;
        gemm_tc<<<dim3(2, NDRUG / 128), 256, GEMM_SMEM, s>>>(
            agg2, wt + (size_t)(8 + i) * DD,
            x2in, wt + (size_t)(10 + i) * DD,
            xdrug, wt + (size_t)(12 + i) * DD,
            bl2 + (size_t)i * D, outp, NDRUG, 3);
        x2in = x2b;
    }
}

// round 5
// speedup vs baseline: 5.6344x; 1.2180x over previous
#include <cuda_runtime.h>
#include <cstdint>

#define D      256
#define N1C    50000
#define E1C    800000
#define NDRUG  4096
#define E2C    131072
#define DD     (D*D)

// ---------------- scratch (device globals; no allocation allowed) -------------
__device__ float g_x[(size_t)N1C * D];
__device__ float g_y[(size_t)N1C * D];
__device__ float g_agg[(size_t)N1C * D];
__device__ float g_gmax[NDRUG * D];
__device__ float g_gmean[NDRUG * D];
__device__ float g_xdrug[NDRUG * D];
__device__ float g_x2a[NDRUG * D];
__device__ float g_x2b[NDRUG * D];
__device__ float g_agg2[NDRUG * D];
__device__ float g_wt[14 * DD];          // transposed (and tf32-rounded) weights

__device__ int g_cnt1i[N1C];
__device__ int g_base1[N1C + 1];
__device__ int g_cur1[N1C];
__device__ int g_csr1[E1C];
__device__ int g_part1[64];

__device__ int g_cnt2i[NDRUG];
__device__ int g_base2[NDRUG + 1];
__device__ int g_cur2[NDRUG];
__device__ int g_csr2[E2C];
__device__ int g_part2[64];

__device__ int g_bounds[NDRUG + 1];

// ---------------- helpers -----------------------------------------------------
__device__ __forceinline__ uint32_t f2tf(float x) {   // round-to-nearest tf32 bits
    uint32_t u;
    asm("cvt.rna.tf32.f32 %0, %1;" : "=r"(u) : "f"(x));
    return u;
}

__device__ __forceinline__ void mma_tf32(float* c, const uint32_t* a, const uint32_t* b) {
    asm volatile(
        "mma.sync.aligned.m16n8k8.row.col.f32.tf32.tf32.f32 "
        "{%0,%1,%2,%3}, {%4,%5,%6,%7}, {%8,%9}, {%0,%1,%2,%3};"
        : "+f"(c[0]), "+f"(c[1]), "+f"(c[2]), "+f"(c[3])
        : "r"(a[0]), "r"(a[1]), "r"(a[2]), "r"(a[3]), "r"(b[0]), "r"(b[1]));
}

__device__ __forceinline__ void cp_async16(uint32_t sa, const void* g) {
    asm volatile("cp.async.cg.shared.global [%0], [%1], 16;" :: "r"(sa), "l"(g));
}
#define CP_COMMIT() asm volatile("cp.async.commit_group;" ::: "memory")
#define CP_WAIT0()  asm volatile("cp.async.wait_group 0;" ::: "memory")

// ---------------- tensor-core GEMM (mma.sync tf32) -----------------------------
// C[M,256] = relu( sum_s A_s[M,256] @ B_s^T + bias ),  B_s given as [256,256]
// row-major [N][K], pre-transposed and tf32-rounded.
// BM=128, BN=128, BK=32; 256 threads; warp grid 2(M) x 4(N); warp tile 64x32.
#define SMSTRIDE 36
#define TILE_F   (128 * SMSTRIDE)
#define GEMM_SMEM (4 * TILE_F * 4)

__global__ void __launch_bounds__(256, 2) gemm_tc(
    const float* A0, const float* B0,
    const float* A1, const float* B1,
    const float* A2, const float* B2,
    const float* __restrict__ bias,
    float* __restrict__ C, int M, int nseg) {
    extern __shared__ float sm[];
    float* As = sm;                    // [2][128][36]
    float* Bs = sm + 2 * TILE_F;       // [2][128][36]

    const int tid = threadIdx.x;
    const int wid = tid >> 5;
    const int lane = tid & 31;
    const int g = lane >> 2;
    const int tq = lane & 3;
    const int wm = (wid >> 2) * 64;
    const int wn = (wid & 3) * 32;
    const int m0 = blockIdx.y * 128;
    const int n0 = blockIdx.x * 128;

    int srow[4], sf4[4];
    uint32_t bsa[2][4];
#pragma unroll
    for (int it = 0; it < 4; it++) {
        int idx = tid + it * 256;
        srow[it] = idx >> 3;
        sf4[it] = idx & 7;
        bsa[0][it] = (uint32_t)__cvta_generic_to_shared(
            Bs + srow[it] * SMSTRIDE + sf4[it] * 4);
        bsa[1][it] = bsa[0][it] + TILE_F * 4;
    }

    float acc[4][4][4];
#pragma unroll
    for (int mt = 0; mt < 4; mt++)
#pragma unroll
        for (int nt = 0; nt < 4; nt++)
#pragma unroll
            for (int q = 0; q < 4; q++) acc[mt][nt][q] = 0.f;

    const float* Aseg[3] = { A0, A1, A2 };
    const float* Bseg[3] = { B0, B1, B2 };
    const int total = nseg * 8;

    float4 av[4];

    // prologue: tile 0
    {
        const float* A = Aseg[0];
        const float* B = Bseg[0];
#pragma unroll
        for (int it = 0; it < 4; it++) {
            cp_async16(bsa[0][it], B + (size_t)(n0 + srow[it]) * D + sf4[it] * 4);
            int gm = m0 + srow[it];
            float4 f = (gm < M) ? *(const float4*)(A + (size_t)gm * D + sf4[it] * 4)
                                : make_float4(0.f, 0.f, 0.f, 0.f);
            uint4 u;
            u.x = f2tf(f.x); u.y = f2tf(f.y); u.z = f2tf(f.z); u.w = f2tf(f.w);
            *(uint4*)(As + srow[it] * SMSTRIDE + sf4[it] * 4) = u;
        }
        CP_COMMIT();
        CP_WAIT0();
    }
    __syncthreads();

    for (int t = 0; t < total; t++) {
        const int buf = t & 1;
        if (t + 1 < total) {
            const float* A = Aseg[(t + 1) >> 3];
            const float* B = Bseg[(t + 1) >> 3];
            const int kc = (t + 1) & 7;
#pragma unroll
            for (int it = 0; it < 4; it++) {
                cp_async16(bsa[buf ^ 1][it],
                           B + (size_t)(n0 + srow[it]) * D + kc * 32 + sf4[it] * 4);
                int gm = m0 + srow[it];
                av[it] = (gm < M) ? *(const float4*)(A + (size_t)gm * D + kc * 32 + sf4[it] * 4)
                                  : make_float4(0.f, 0.f, 0.f, 0.f);
            }
            CP_COMMIT();
        }

        const float* Ab = As + buf * TILE_F;
        const float* Bb = Bs + buf * TILE_F;
#pragma unroll
        for (int k8 = 0; k8 < 4; k8++) {
            const int kb = k8 * 8;
            uint32_t af[4][4], bf[4][2];
#pragma unroll
            for (int mt = 0; mt < 4; mt++) {
                int r = wm + mt * 16 + g;
                af[mt][0] = __float_as_uint(Ab[r * SMSTRIDE + kb + tq]);
                af[mt][1] = __float_as_uint(Ab[(r + 8) * SMSTRIDE + kb + tq]);
                af[mt][2] = __float_as_uint(Ab[r * SMSTRIDE + kb + tq + 4]);
                af[mt][3] = __float_as_uint(Ab[(r + 8) * SMSTRIDE + kb + tq + 4]);
            }
#pragma unroll
            for (int nt = 0; nt < 4; nt++) {
                int n = wn + nt * 8 + g;
                bf[nt][0] = __float_as_uint(Bb[n * SMSTRIDE + kb + tq]);
                bf[nt][1] = __float_as_uint(Bb[n * SMSTRIDE + kb + tq + 4]);
            }
#pragma unroll
            for (int mt = 0; mt < 4; mt++)
#pragma unroll
                for (int nt = 0; nt < 4; nt++)
                    mma_tf32(acc[mt][nt], af[mt], bf[nt]);
        }

        if (t + 1 < total) {
            __syncthreads();
            float* An = As + (buf ^ 1) * TILE_F;
#pragma unroll
            for (int it = 0; it < 4; it++) {
                uint4 u;
                u.x = f2tf(av[it].x); u.y = f2tf(av[it].y);
                u.z = f2tf(av[it].z); u.w = f2tf(av[it].w);
                *(uint4*)(An + srow[it] * SMSTRIDE + sf4[it] * 4) = u;
            }
            CP_WAIT0();
            __syncthreads();
        }
    }

    // epilogue
#pragma unroll
    for (int mt = 0; mt < 4; mt++) {
        int mlo = m0 + wm + mt * 16 + g;
#pragma unroll
        for (int nt = 0; nt < 4; nt++) {
            int n = n0 + wn + nt * 8 + tq * 2;
            float b0 = bias[n], b1 = bias[n + 1];
            if (mlo < M) {
                float2 o;
                o.x = fmaxf(acc[mt][nt][0] + b0, 0.f);
                o.y = fmaxf(acc[mt][nt][1] + b1, 0.f);
                *(float2*)(C + (size_t)mlo * D + n) = o;
            }
            if (mlo + 8 < M) {
                float2 o;
                o.x = fmaxf(acc[mt][nt][2] + b0, 0.f);
                o.y = fmaxf(acc[mt][nt][3] + b1, 0.f);
                *(float2*)(C + (size_t)(mlo + 8) * D + n) = o;
            }
        }
    }
}

// ---------------- weight transpose (+ tf32 rounding) --------------------------
struct WTP { const float* src[14]; float* dst[14]; };

__global__ void transpose_tf32(WTP p) {
    __shared__ float t[32][33];
    const float* src = p.src[blockIdx.z];
    float* dst = p.dst[blockIdx.z];
    int x = blockIdx.x * 32 + threadIdx.x;
    int y0 = blockIdx.y * 32 + threadIdx.y;
#pragma unroll
    for (int i = 0; i < 32; i += 8)
        t[threadIdx.y + i][threadIdx.x] = src[(size_t)(y0 + i) * D + x];
    __syncthreads();
    int x2 = blockIdx.y * 32 + threadIdx.x;
    int y2 = blockIdx.x * 32 + threadIdx.y;
#pragma unroll
    for (int i = 0; i < 32; i += 8) {
        uint32_t u = f2tf(t[threadIdx.x][threadIdx.y + i]);
        dst[(size_t)(y2 + i) * D + x2] = __uint_as_float(u);
    }
}

// ---------------- scan (3-phase) ----------------------------------------------
__global__ void __launch_bounds__(1024) scan_block(
    const int* __restrict__ cnt, int* __restrict__ out,
    int* __restrict__ partial, int n) {
    __shared__ int ws[32];
    int i = blockIdx.x * 1024 + threadIdx.x;
    int lane = threadIdx.x & 31, w = threadIdx.x >> 5;
    int v = (i < n) ? cnt[i] : 0;
    int x = v;
#pragma unroll
    for (int o = 1; o < 32; o <<= 1) {
        int y = __shfl_up_sync(0xffffffffu, x, o);
        if (lane >= o) x += y;
    }
    if (lane == 31) ws[w] = x;
    __syncthreads();
    if (w == 0) {
        int t = ws[lane];
#pragma unroll
        for (int o = 1; o < 32; o <<= 1) {
            int y = __shfl_up_sync(0xffffffffu, t, o);
            if (lane >= o) t += y;
        }
        ws[lane] = t;
    }
    __syncthreads();
    int excl = x - v + (w ? ws[w - 1] : 0);
    if (i < n) out[i] = excl;
    if (threadIdx.x == 1023) partial[blockIdx.x] = excl + v;
}

__global__ void __launch_bounds__(128) scan_partial(
    int* __restrict__ partial, int* __restrict__ base_n, int nb) {
    __shared__ int sh[128];
    int tid = threadIdx.x;
    int v = (tid < nb) ? partial[tid] : 0;
    sh[tid] = v;
    __syncthreads();
#pragma unroll
    for (int o = 1; o < 128; o <<= 1) {
        int t = (tid >= o) ? sh[tid - o] : 0;
        __syncthreads();
        sh[tid] += t;
        __syncthreads();
    }
    if (tid < nb) partial[tid] = sh[tid] - v;   // exclusive
    if (tid == 127) *base_n = sh[127];          // total -> base[n]
}

__global__ void __launch_bounds__(1024) add_offsets(
    int* __restrict__ base, int* __restrict__ cur,
    const int* __restrict__ partial, int n) {
    int i = blockIdx.x * 1024 + threadIdx.x;
    if (i < n) {
        int v = base[i] + partial[blockIdx.x];
        base[i] = v;
        cur[i] = v;
    }
}

// ---------------- small kernels ------------------------------------------------
__global__ void gather_rows(const float* __restrict__ emb, const int* __restrict__ ids,
                            float* __restrict__ out, int n) {
    int t = blockIdx.x * blockDim.x + threadIdx.x;
    int i = t >> 6, c = t & 63;
    if (i >= n) return;
    float4 v = ((const float4*)(emb + (size_t)ids[i] * D))[c];
    ((float4*)(out + (size_t)i * D))[c] = v;
}

__global__ void gather2_rows(const float* __restrict__ xdrug, const float* __restrict__ emb2,
                             const int* __restrict__ ids, float* __restrict__ out) {
    int t = blockIdx.x * blockDim.x + threadIdx.x;
    int i = t >> 6, c = t & 63;
    if (i >= NDRUG) return;
    int id = ids[i];
    const float* src = (id < NDRUG) ? (xdrug + (size_t)id * D) : (emb2 + (size_t)id * D);
    ((float4*)(out + (size_t)i * D))[c] = ((const float4*)src)[c];
}

__global__ void count_int(const int* __restrict__ dst, int* __restrict__ cnt, int n) {
    int e = blockIdx.x * blockDim.x + threadIdx.x;
    if (e < n) atomicAdd(&cnt[dst[e]], 1);
}

__global__ void fill_csr(const int* __restrict__ src, const int* __restrict__ dst,
                         int* __restrict__ cursor, int* __restrict__ csr, int E) {
    int e = blockIdx.x * blockDim.x + threadIdx.x;
    if (e >= E) return;
    int p = atomicAdd(&cursor[dst[e]], 1);
    csr[p] = src[e];
}

// warp-per-node mean aggregation over CSR, 2-edge unrolled for MLP.
__global__ void __launch_bounds__(256) aggregate(
    const float* __restrict__ x, const int* __restrict__ csr,
    const int* __restrict__ base, float* __restrict__ agg, int n) {
    int node = blockIdx.x * 8 + (threadIdx.x >> 5);
    int lane = threadIdx.x & 31;
    if (node >= n) return;
    int lo = base[node], hi = base[node + 1];
    float4 a0 = make_float4(0.f, 0.f, 0.f, 0.f);
    float4 a1 = make_float4(0.f, 0.f, 0.f, 0.f);
    int j = lo;
    for (; j + 1 < hi; j += 2) {
        int s0 = csr[j], s1 = csr[j + 1];
        const float4* r0 = (const float4*)(x + (size_t)s0 * D);
        const float4* r1 = (const float4*)(x + (size_t)s1 * D);
        float4 v00 = r0[lane];
        float4 v01 = r0[lane + 32];
        float4 v10 = r1[lane];
        float4 v11 = r1[lane + 32];
        a0.x += v00.x + v10.x; a0.y += v00.y + v10.y;
        a0.z += v00.z + v10.z; a0.w += v00.w + v10.w;
        a1.x += v01.x + v11.x; a1.y += v01.y + v11.y;
        a1.z += v01.z + v11.z; a1.w += v01.w + v11.w;
    }
    if (j < hi) {
        int s0 = csr[j];
        const float4* r0 = (const float4*)(x + (size_t)s0 * D);
        float4 v00 = r0[lane];
        float4 v01 = r0[lane + 32];
        a0.x += v00.x; a0.y += v00.y; a0.z += v00.z; a0.w += v00.w;
        a1.x += v01.x; a1.y += v01.y; a1.z += v01.z; a1.w += v01.w;
    }
    float r = 1.f / fmaxf((float)(hi - lo), 1.f);
    a0.x *= r; a0.y *= r; a0.z *= r; a0.w *= r;
    a1.x *= r; a1.y *= r; a1.z *= r; a1.w *= r;
    float4* out = (float4*)(agg + (size_t)node * D);
    out[lane] = a0;
    out[lane + 32] = a1;
}

__global__ void seg_bounds(const int* __restrict__ batch, int* __restrict__ bounds,
                           int n, int nseg) {
    int b = blockIdx.x * blockDim.x + threadIdx.x;
    if (b > nseg) return;
    int lo = 0, hi = n;
    while (lo < hi) {
        int mid = (lo + hi) >> 1;
        if (batch[mid] < b) lo = mid + 1; else hi = mid;
    }
    bounds[b] = lo;
}

__global__ void __launch_bounds__(256) pool2(
    const float* __restrict__ x, const int* __restrict__ bounds,
    float* __restrict__ gmax, float* __restrict__ gmean) {
    int drug = blockIdx.x * 8 + (threadIdx.x >> 5);
    int lane = threadIdx.x & 31;
    if (drug >= NDRUG) return;
    int lo = bounds[drug], hi = bounds[drug + 1];
    float4 m0 = make_float4(0.f, 0.f, 0.f, 0.f);
    float4 m1 = make_float4(0.f, 0.f, 0.f, 0.f);
    float4 s0 = make_float4(0.f, 0.f, 0.f, 0.f);
    float4 s1 = make_float4(0.f, 0.f, 0.f, 0.f);
    for (int i = lo; i < hi; i++) {
        const float4* row = (const float4*)(x + (size_t)i * D);
        float4 v0 = row[lane];
        float4 v1 = row[lane + 32];
        m0.x = fmaxf(m0.x, v0.x); m0.y = fmaxf(m0.y, v0.y);
        m0.z = fmaxf(m0.z, v0.z); m0.w = fmaxf(m0.w, v0.w);
        m1.x = fmaxf(m1.x, v1.x); m1.y = fmaxf(m1.y, v1.y);
        m1.z = fmaxf(m1.z, v1.z); m1.w = fmaxf(m1.w, v1.w);
        s0.x += v0.x; s0.y += v0.y; s0.z += v0.z; s0.w += v0.w;
        s1.x += v1.x; s1.y += v1.y; s1.z += v1.z; s1.w += v1.w;
    }
    float r = 1.f / fmaxf((float)(hi - lo), 1.f);
    s0.x *= r; s0.y *= r; s0.z *= r; s0.w *= r;
    s1.x *= r; s1.y *= r; s1.z *= r; s1.w *= r;
    float4* om = (float4*)(gmax + (size_t)drug * D);
    float4* os = (float4*)(gmean + (size_t)drug * D);
    om[lane] = m0; om[lane + 32] = m1;
    os[lane] = s0; os[lane + 32] = s1;
}

// ---------------- launch ------------------------------------------------------
extern "C" void kernel_launch(void* const* d_in, const int* in_sizes, int n_in,
                              void* d_out, int out_size) {
    const int* x1    = (const int*)d_in[0];
    const int* ei1   = (const int*)d_in[1];
    const int* batch = (const int*)d_in[2];
    const int* x2ids = (const int*)d_in[3];
    const int* ei2   = (const int*)d_in[4];
    const float* emb1  = (const float*)d_in[5];
    const float* emb2  = (const float*)d_in[6];
    const float* Wl1   = (const float*)d_in[7];
    const float* bl1   = (const float*)d_in[8];
    const float* Wr1   = (const float*)d_in[9];
    const float* lin1W = (const float*)d_in[10];
    const float* lin1b = (const float*)d_in[11];
    const float* Wl2   = (const float*)d_in[12];
    const float* bl2   = (const float*)d_in[13];
    const float* Wr2   = (const float*)d_in[14];
    const float* Wx2   = (const float*)d_in[15];

    const int* src1 = ei1;
    const int* dst1 = ei1 + E1C;
    const int* src2 = ei2;
    const int* dst2 = ei2 + E2C;

    float *x, *y, *agg, *gmax, *gmean, *xdrug, *x2a, *x2b, *agg2, *wt;
    int *cnt1i, *base1, *cur1, *csr1, *part1;
    int *cnt2i, *base2, *cur2, *csr2, *part2, *bounds;
    cudaGetSymbolAddress((void**)&x, g_x);
    cudaGetSymbolAddress((void**)&y, g_y);
    cudaGetSymbolAddress((void**)&agg, g_agg);
    cudaGetSymbolAddress((void**)&gmax, g_gmax);
    cudaGetSymbolAddress((void**)&gmean, g_gmean);
    cudaGetSymbolAddress((void**)&xdrug, g_xdrug);
    cudaGetSymbolAddress((void**)&x2a, g_x2a);
    cudaGetSymbolAddress((void**)&x2b, g_x2b);
    cudaGetSymbolAddress((void**)&agg2, g_agg2);
    cudaGetSymbolAddress((void**)&wt, g_wt);
    cudaGetSymbolAddress((void**)&cnt1i, g_cnt1i);
    cudaGetSymbolAddress((void**)&base1, g_base1);
    cudaGetSymbolAddress((void**)&cur1, g_cur1);
    cudaGetSymbolAddress((void**)&csr1, g_csr1);
    cudaGetSymbolAddress((void**)&part1, g_part1);
    cudaGetSymbolAddress((void**)&cnt2i, g_cnt2i);
    cudaGetSymbolAddress((void**)&base2, g_base2);
    cudaGetSymbolAddress((void**)&cur2, g_cur2);
    cudaGetSymbolAddress((void**)&csr2, g_csr2);
    cudaGetSymbolAddress((void**)&part2, g_part2);
    cudaGetSymbolAddress((void**)&bounds, g_bounds);

    cudaFuncSetAttribute(gemm_tc, cudaFuncAttributeMaxDynamicSharedMemorySize, GEMM_SMEM);

    cudaStream_t s = 0;

    // ---- weight transposes (+ tf32 rounding), once per call ----
    WTP wp;
    for (int i = 0; i < 3; i++) { wp.src[i]     = Wl1 + (size_t)i * DD; }
    for (int i = 0; i < 3; i++) { wp.src[3 + i] = Wr1 + (size_t)i * DD; }
    wp.src[6] = lin1W;
    wp.src[7] = lin1W + (size_t)DD;
    for (int i = 0; i < 2; i++) { wp.src[8 + i]  = Wl2 + (size_t)i * DD; }
    for (int i = 0; i < 2; i++) { wp.src[10 + i] = Wr2 + (size_t)i * DD; }
    for (int i = 0; i < 2; i++) { wp.src[12 + i] = Wx2 + (size_t)i * DD; }
    for (int i = 0; i < 14; i++) wp.dst[i] = wt + (size_t)i * DD;
    transpose_tf32<<<dim3(8, 8, 14), dim3(32, 8), 0, s>>>(wp);

    // ---- CSR build for both graphs ----
    const int nb1 = (N1C + 1023) / 1024;       // 49
    const int nb2 = (NDRUG + 1023) / 1024;     // 4
    cudaMemsetAsync(cnt1i, 0, N1C * sizeof(int), s);
    cudaMemsetAsync(cnt2i, 0, NDRUG * sizeof(int), s);
    count_int<<<(E1C + 255) / 256, 256, 0, s>>>(dst1, cnt1i, E1C);
    count_int<<<(E2C + 255) / 256, 256, 0, s>>>(dst2, cnt2i, E2C);
    scan_block<<<nb1, 1024, 0, s>>>(cnt1i, base1, part1, N1C);
    scan_block<<<nb2, 1024, 0, s>>>(cnt2i, base2, part2, NDRUG);
    scan_partial<<<1, 128, 0, s>>>(part1, base1 + N1C, nb1);
    scan_partial<<<1, 128, 0, s>>>(part2, base2 + NDRUG, nb2);
    add_offsets<<<nb1, 1024, 0, s>>>(base1, cur1, part1, N1C);
    add_offsets<<<nb2, 1024, 0, s>>>(base2, cur2, part2, NDRUG);
    fill_csr<<<(E1C + 255) / 256, 256, 0, s>>>(src1, dst1, cur1, csr1, E1C);
    fill_csr<<<(E2C + 255) / 256, 256, 0, s>>>(src2, dst2, cur2, csr2, E2C);
    seg_bounds<<<(NDRUG + 1 + 255) / 256, 256, 0, s>>>(batch, bounds, N1C, NDRUG);

    // ---- level 1 ----
    gather_rows<<<((size_t)N1C * 64 + 255) / 256, 256, 0, s>>>(emb1, x1, x, N1C);

    float* xin = x;
    float* xout = y;
    const dim3 gg1(2, (N1C + 127) / 128);
    for (int i = 0; i < 3; i++) {
        aggregate<<<(N1C + 7) / 8, 256, 0, s>>>(xin, csr1, base1, agg, N1C);
        gemm_tc<<<gg1, 256, GEMM_SMEM, s>>>(
            agg, wt + (size_t)i * DD,
            xin, wt + (size_t)(3 + i) * DD,
            nullptr, nullptr,
            bl1 + (size_t)i * D, xout, N1C, 2);
        float* t = xin; xin = xout; xout = t;
    }

    // ---- pooling + lin1 ----
    pool2<<<NDRUG / 8, 256, 0, s>>>(xin, bounds, gmax, gmean);
    gemm_tc<<<dim3(2, NDRUG / 128), 256, GEMM_SMEM, s>>>(
        gmax, wt + (size_t)6 * DD,
        gmean, wt + (size_t)7 * DD,
        nullptr, nullptr,
        lin1b, xdrug, NDRUG, 2);

    // ---- level 2 ----
    gather2_rows<<<((size_t)NDRUG * 64 + 255) / 256, 256, 0, s>>>(xdrug, emb2, x2ids, x2a);
    float* x2in = x2a;
    for (int i = 0; i < 2; i++) {
        aggregate<<<(NDRUG + 7) / 8, 256, 0, s>>>(x2in, csr2, base2, agg2, NDRUG);
        float* outp = (i == 1) ? (float*)d_out : x2b;
        gemm_tc<<<dim3(2, NDRUG / 128), 256, GEMM_SMEM, s>>>(
            agg2, wt + (size_t)(8 + i) * DD,
            x2in, wt + (size_t)(10 + i) * DD,
            xdrug, wt + (size_t)(12 + i) * DD,
            bl2 + (size_t)i * D, outp, NDRUG, 3);
        x2in = x2b;
    }
}

// round 6
// speedup vs baseline: 8.0609x; 1.4307x over previous
#include <cuda_runtime.h>
#include <cuda_fp16.h>
#include <cstdint>

#define D      256
#define N1C    50000
#define E1C    800000
#define NDRUG  4096
#define E2C    131072
#define DD     (D*D)

// ---------------- scratch (device globals; no allocation allowed) -------------
__device__ __half h_x[(size_t)N1C * D];
__device__ __half h_y[(size_t)N1C * D];
__device__ __half h_agg[(size_t)N1C * D];
__device__ __half h_gmax[NDRUG * D];
__device__ __half h_gmean[NDRUG * D];
__device__ __half h_xdrug[NDRUG * D];
__device__ __half h_x2a[NDRUG * D];
__device__ __half h_x2b[NDRUG * D];
__device__ __half h_agg2[NDRUG * D];
__device__ __half h_wt[14 * DD];          // transposed fp16 weights [N][K]

__device__ int g_cnt1i[N1C];
__device__ int g_base1[N1C + 1];
__device__ int g_cur1[N1C];
__device__ int g_csr1[E1C];
__device__ int g_part1[64];

__device__ int g_cnt2i[NDRUG];
__device__ int g_base2[NDRUG + 1];
__device__ int g_cur2[NDRUG];
__device__ int g_csr2[E2C];
__device__ int g_part2[64];

__device__ int g_bounds[NDRUG + 1];

// ---------------- PTX helpers --------------------------------------------------
__device__ __forceinline__ void cp_async_z(uint32_t sa, const void* g, int sz) {
    asm volatile("cp.async.cg.shared.global [%0], [%1], 16, %2;"
                 :: "r"(sa), "l"(g), "r"(sz));
}
#define CP_COMMIT() asm volatile("cp.async.commit_group;" ::: "memory")
#define CP_WAIT0()  asm volatile("cp.async.wait_group 0;" ::: "memory")

__device__ __forceinline__ void ldm_x4(uint32_t* r, uint32_t addr) {
    asm volatile("ldmatrix.sync.aligned.m8n8.x4.shared.b16 {%0,%1,%2,%3}, [%4];"
                 : "=r"(r[0]), "=r"(r[1]), "=r"(r[2]), "=r"(r[3]) : "r"(addr));
}
__device__ __forceinline__ void ldm_x2(uint32_t* r, uint32_t addr) {
    asm volatile("ldmatrix.sync.aligned.m8n8.x2.shared.b16 {%0,%1}, [%2];"
                 : "=r"(r[0]), "=r"(r[1]) : "r"(addr));
}
__device__ __forceinline__ void mma_f16(float* c, const uint32_t* a, const uint32_t* b) {
    asm volatile(
        "mma.sync.aligned.m16n8k16.row.col.f32.f16.f16.f32 "
        "{%0,%1,%2,%3}, {%4,%5,%6,%7}, {%8,%9}, {%0,%1,%2,%3};"
        : "+f"(c[0]), "+f"(c[1]), "+f"(c[2]), "+f"(c[3])
        : "r"(a[0]), "r"(a[1]), "r"(a[2]), "r"(a[3]), "r"(b[0]), "r"(b[1]));
}

// ---------------- fp16 tensor-core GEMM ----------------------------------------
// C[M,256] = relu( sum_s A_s[M,256] @ B_s^T + bias ), A fp16, B fp16 [N][K].
// BM=128, BN=128, BK=32(halves); 256 threads; warps 2(M) x 4(N); warp tile 64x32.
// SMEM row = 80 bytes (64 data + 16 pad) -> ldmatrix conflict-free.
#define ROWB 80
#define TILE_B (128 * ROWB)                 // 10240 bytes per buffer
#define GEMM_SMEM (4 * TILE_B)              // A0,A1,B0,B1

__global__ void __launch_bounds__(256, 2) gemm_h(
    const __half* A0, const __half* B0,
    const __half* A1, const __half* B1,
    const __half* A2, const __half* B2,
    const float* __restrict__ bias,
    float* __restrict__ Cf, __half* __restrict__ Ch, int M, int nseg) {
    extern __shared__ char sm[];
    const uint32_t smBase = (uint32_t)__cvta_generic_to_shared(sm);
    const uint32_t aBase[2] = { smBase, smBase + TILE_B };
    const uint32_t bBase[2] = { smBase + 2 * TILE_B, smBase + 3 * TILE_B };

    const int tid = threadIdx.x;
    const int wid = tid >> 5;
    const int lane = tid & 31;
    const int g = lane >> 2;
    const int tq = lane & 3;
    const int wm = (wid >> 2) * 64;
    const int wn = (wid & 3) * 32;
    const int m0 = blockIdx.y * 128;
    const int n0 = blockIdx.x * 128;

    // ldmatrix per-thread smem offsets (within a buffer)
    uint32_t aoff[4], boff[4];
#pragma unroll
    for (int mt = 0; mt < 4; mt++)
        aoff[mt] = (uint32_t)((wm + mt * 16 + (lane & 15)) * ROWB + ((lane & 16) ? 16 : 0));
#pragma unroll
    for (int nt = 0; nt < 4; nt++)
        boff[nt] = (uint32_t)((wn + nt * 8 + (lane & 7)) * ROWB + ((lane & 8) ? 16 : 0));

    float acc[4][4][4];
#pragma unroll
    for (int mt = 0; mt < 4; mt++)
#pragma unroll
        for (int nt = 0; nt < 4; nt++)
#pragma unroll
            for (int q = 0; q < 4; q++) acc[mt][nt][q] = 0.f;

    const __half* Aseg[3] = { A0, A1, A2 };
    const __half* Bseg[3] = { B0, B1, B2 };
    const int total = nseg * 8;

    // staging: thread covers 2 16B chunks of A and 2 of B per tile
    const int c0i = tid * 2;
    const int row0 = c0i >> 2, off0 = (c0i & 3) * 16;
    const int row1 = (c0i + 1) >> 2, off1 = ((c0i + 1) & 3) * 16;

#define STAGE(buf, tile) do { \
    const __half* A = Aseg[(tile) >> 3]; \
    const __half* B = Bseg[(tile) >> 3]; \
    const int kh = ((tile) & 7) * 32; \
    cp_async_z(aBase[buf] + row0 * ROWB + off0, \
               (const char*)(A + (size_t)(m0 + row0) * D + kh) + off0, \
               (m0 + row0 < M) ? 16 : 0); \
    cp_async_z(aBase[buf] + row1 * ROWB + off1, \
               (const char*)(A + (size_t)(m0 + row1) * D + kh) + off1, \
               (m0 + row1 < M) ? 16 : 0); \
    cp_async_z(bBase[buf] + row0 * ROWB + off0, \
               (const char*)(B + (size_t)(n0 + row0) * D + kh) + off0, 16); \
    cp_async_z(bBase[buf] + row1 * ROWB + off1, \
               (const char*)(B + (size_t)(n0 + row1) * D + kh) + off1, 16); \
    CP_COMMIT(); \
} while (0)

    STAGE(0, 0);
    CP_WAIT0();
    __syncthreads();

    for (int t = 0; t < total; t++) {
        const int buf = t & 1;
        if (t + 1 < total) STAGE(buf ^ 1, t + 1);

        const uint32_t Ab = aBase[buf], Bb = bBase[buf];
#pragma unroll
        for (int ks = 0; ks < 2; ks++) {
            uint32_t af[4][4], bf[4][2];
#pragma unroll
            for (int mt = 0; mt < 4; mt++) ldm_x4(af[mt], Ab + aoff[mt] + ks * 32);
#pragma unroll
            for (int nt = 0; nt < 4; nt++) ldm_x2(bf[nt], Bb + boff[nt] + ks * 32);
#pragma unroll
            for (int mt = 0; mt < 4; mt++)
#pragma unroll
                for (int nt = 0; nt < 4; nt++)
                    mma_f16(acc[mt][nt], af[mt], bf[nt]);
        }

        if (t + 1 < total) {
            CP_WAIT0();
            __syncthreads();
        }
    }

    // epilogue: bias + relu
#pragma unroll
    for (int mt = 0; mt < 4; mt++) {
        int mlo = m0 + wm + mt * 16 + g;
#pragma unroll
        for (int nt = 0; nt < 4; nt++) {
            int n = n0 + wn + nt * 8 + tq * 2;
            float b0 = bias[n], b1 = bias[n + 1];
            float o0 = fmaxf(acc[mt][nt][0] + b0, 0.f);
            float o1 = fmaxf(acc[mt][nt][1] + b1, 0.f);
            float o2 = fmaxf(acc[mt][nt][2] + b0, 0.f);
            float o3 = fmaxf(acc[mt][nt][3] + b1, 0.f);
            if (Ch) {
                if (mlo < M)
                    *(__half2*)(Ch + (size_t)mlo * D + n) =
                        __float22half2_rn(make_float2(o0, o1));
                if (mlo + 8 < M)
                    *(__half2*)(Ch + (size_t)(mlo + 8) * D + n) =
                        __float22half2_rn(make_float2(o2, o3));
            } else {
                if (mlo < M)
                    *(float2*)(Cf + (size_t)mlo * D + n) = make_float2(o0, o1);
                if (mlo + 8 < M)
                    *(float2*)(Cf + (size_t)(mlo + 8) * D + n) = make_float2(o2, o3);
            }
        }
    }
}

// ---------------- weight transpose (fp32 -> fp16, [K][N] -> [N][K]) ------------
struct WTP { const float* src[14]; __half* dst[14]; };

__global__ void transpose_h(WTP p) {
    __shared__ float t[32][33];
    const float* src = p.src[blockIdx.z];
    __half* dst = p.dst[blockIdx.z];
    int x = blockIdx.x * 32 + threadIdx.x;
    int y0 = blockIdx.y * 32 + threadIdx.y;
#pragma unroll
    for (int i = 0; i < 32; i += 8)
        t[threadIdx.y + i][threadIdx.x] = src[(size_t)(y0 + i) * D + x];
    __syncthreads();
    int x2 = blockIdx.y * 32 + threadIdx.x;
    int y2 = blockIdx.x * 32 + threadIdx.y;
#pragma unroll
    for (int i = 0; i < 32; i += 8)
        dst[(size_t)(y2 + i) * D + x2] = __float2half_rn(t[threadIdx.x][threadIdx.y + i]);
}

// ---------------- scan (3-phase) ------------------------------------------------
__global__ void __launch_bounds__(1024) scan_block(
    const int* __restrict__ cnt, int* __restrict__ out,
    int* __restrict__ partial, int n) {
    __shared__ int ws[32];
    int i = blockIdx.x * 1024 + threadIdx.x;
    int lane = threadIdx.x & 31, w = threadIdx.x >> 5;
    int v = (i < n) ? cnt[i] : 0;
    int x = v;
#pragma unroll
    for (int o = 1; o < 32; o <<= 1) {
        int y = __shfl_up_sync(0xffffffffu, x, o);
        if (lane >= o) x += y;
    }
    if (lane == 31) ws[w] = x;
    __syncthreads();
    if (w == 0) {
        int t = ws[lane];
#pragma unroll
        for (int o = 1; o < 32; o <<= 1) {
            int y = __shfl_up_sync(0xffffffffu, t, o);
            if (lane >= o) t += y;
        }
        ws[lane] = t;
    }
    __syncthreads();
    int excl = x - v + (w ? ws[w - 1] : 0);
    if (i < n) out[i] = excl;
    if (threadIdx.x == 1023) partial[blockIdx.x] = excl + v;
}

__global__ void __launch_bounds__(128) scan_partial(
    int* __restrict__ partial, int* __restrict__ base_n, int nb) {
    __shared__ int sh[128];
    int tid = threadIdx.x;
    int v = (tid < nb) ? partial[tid] : 0;
    sh[tid] = v;
    __syncthreads();
#pragma unroll
    for (int o = 1; o < 128; o <<= 1) {
        int t = (tid >= o) ? sh[tid - o] : 0;
        __syncthreads();
        sh[tid] += t;
        __syncthreads();
    }
    if (tid < nb) partial[tid] = sh[tid] - v;
    if (tid == 127) *base_n = sh[127];
}

__global__ void __launch_bounds__(1024) add_offsets(
    int* __restrict__ base, int* __restrict__ cur,
    const int* __restrict__ partial, int n) {
    int i = blockIdx.x * 1024 + threadIdx.x;
    if (i < n) {
        int v = base[i] + partial[blockIdx.x];
        base[i] = v;
        cur[i] = v;
    }
}

// ---------------- small kernels -------------------------------------------------
// emb fp32 -> out fp16 (64 threads / row, float4 -> half4)
__global__ void gather_rows_h(const float* __restrict__ emb, const int* __restrict__ ids,
                              __half* __restrict__ out, int n) {
    int t = blockIdx.x * blockDim.x + threadIdx.x;
    int i = t >> 6, c = t & 63;
    if (i >= n) return;
    float4 v = ((const float4*)(emb + (size_t)ids[i] * D))[c];
    __half2 h0 = __float22half2_rn(make_float2(v.x, v.y));
    __half2 h1 = __float22half2_rn(make_float2(v.z, v.w));
    uint2 u;
    u.x = *(uint32_t*)&h0;
    u.y = *(uint32_t*)&h1;
    ((uint2*)(out + (size_t)i * D))[c] = u;
}

// x2 init: xdrug (fp16) for ids < NDRUG, emb2 (fp32->fp16) otherwise; 32 thr/row
__global__ void gather2_h(const __half* __restrict__ xdrug, const float* __restrict__ emb2,
                          const int* __restrict__ ids, __half* __restrict__ out) {
    int t = blockIdx.x * blockDim.x + threadIdx.x;
    int i = t >> 5, c = t & 31;
    if (i >= NDRUG) return;
    int id = ids[i];
    uint4 u;
    if (id < NDRUG) {
        u = ((const uint4*)(xdrug + (size_t)id * D))[c];
    } else {
        const float4* r = (const float4*)(emb2 + (size_t)id * D);
        float4 a = r[c * 2], b = r[c * 2 + 1];
        __half2 h0 = __float22half2_rn(make_float2(a.x, a.y));
        __half2 h1 = __float22half2_rn(make_float2(a.z, a.w));
        __half2 h2 = __float22half2_rn(make_float2(b.x, b.y));
        __half2 h3 = __float22half2_rn(make_float2(b.z, b.w));
        u.x = *(uint32_t*)&h0; u.y = *(uint32_t*)&h1;
        u.z = *(uint32_t*)&h2; u.w = *(uint32_t*)&h3;
    }
    ((uint4*)(out + (size_t)i * D))[c] = u;
}

__global__ void count_int(const int* __restrict__ dst, int* __restrict__ cnt, int n) {
    int e = blockIdx.x * blockDim.x + threadIdx.x;
    if (e < n) atomicAdd(&cnt[dst[e]], 1);
}

__global__ void fill_csr(const int* __restrict__ src, const int* __restrict__ dst,
                         int* __restrict__ cursor, int* __restrict__ csr, int E) {
    int e = blockIdx.x * blockDim.x + threadIdx.x;
    if (e >= E) return;
    int p = atomicAdd(&cursor[dst[e]], 1);
    csr[p] = src[e];
}

// warp-per-node mean aggregation (fp16 in/out, fp32 accumulate), 2-edge unroll
__global__ void __launch_bounds__(256) aggregate_h(
    const __half* __restrict__ x, const int* __restrict__ csr,
    const int* __restrict__ base, __half* __restrict__ agg, int n) {
    int node = blockIdx.x * 8 + (threadIdx.x >> 5);
    int lane = threadIdx.x & 31;
    if (node >= n) return;
    int lo = base[node], hi = base[node + 1];
    float2 a0 = make_float2(0.f, 0.f), a1 = a0, a2 = a0, a3 = a0;
    int j = lo;
    for (; j + 1 < hi; j += 2) {
        uint4 v0 = ((const uint4*)(x + (size_t)csr[j] * D))[lane];
        uint4 v1 = ((const uint4*)(x + (size_t)csr[j + 1] * D))[lane];
        float2 f;
        f = __half22float2(*(__half2*)&v0.x); a0.x += f.x; a0.y += f.y;
        f = __half22float2(*(__half2*)&v0.y); a1.x += f.x; a1.y += f.y;
        f = __half22float2(*(__half2*)&v0.z); a2.x += f.x; a2.y += f.y;
        f = __half22float2(*(__half2*)&v0.w); a3.x += f.x; a3.y += f.y;
        f = __half22float2(*(__half2*)&v1.x); a0.x += f.x; a0.y += f.y;
        f = __half22float2(*(__half2*)&v1.y); a1.x += f.x; a1.y += f.y;
        f = __half22float2(*(__half2*)&v1.z); a2.x += f.x; a2.y += f.y;
        f = __half22float2(*(__half2*)&v1.w); a3.x += f.x; a3.y += f.y;
    }
    if (j < hi) {
        uint4 v0 = ((const uint4*)(x + (size_t)csr[j] * D))[lane];
        float2 f;
        f = __half22float2(*(__half2*)&v0.x); a0.x += f.x; a0.y += f.y;
        f = __half22float2(*(__half2*)&v0.y); a1.x += f.x; a1.y += f.y;
        f = __half22float2(*(__half2*)&v0.z); a2.x += f.x; a2.y += f.y;
        f = __half22float2(*(__half2*)&v0.w); a3.x += f.x; a3.y += f.y;
    }
    float r = 1.f / fmaxf((float)(hi - lo), 1.f);
    __half2 h0 = __float22half2_rn(make_float2(a0.x * r, a0.y * r));
    __half2 h1 = __float22half2_rn(make_float2(a1.x * r, a1.y * r));
    __half2 h2 = __float22half2_rn(make_float2(a2.x * r, a2.y * r));
    __half2 h3 = __float22half2_rn(make_float2(a3.x * r, a3.y * r));
    uint4 u;
    u.x = *(uint32_t*)&h0; u.y = *(uint32_t*)&h1;
    u.z = *(uint32_t*)&h2; u.w = *(uint32_t*)&h3;
    ((uint4*)(agg + (size_t)node * D))[lane] = u;
}

__global__ void seg_bounds(const int* __restrict__ batch, int* __restrict__ bounds,
                           int n, int nseg) {
    int b = blockIdx.x * blockDim.x + threadIdx.x;
    if (b > nseg) return;
    int lo = 0, hi = n;
    while (lo < hi) {
        int mid = (lo + hi) >> 1;
        if (batch[mid] < b) lo = mid + 1; else hi = mid;
    }
    bounds[b] = lo;
}

// warp-per-drug max + mean pooling (fp16 in, fp16 out, fp32 math)
__global__ void __launch_bounds__(256) pool2_h(
    const __half* __restrict__ x, const int* __restrict__ bounds,
    __half* __restrict__ gmax, __half* __restrict__ gmean) {
    int drug = blockIdx.x * 8 + (threadIdx.x >> 5);
    int lane = threadIdx.x & 31;
    if (drug >= NDRUG) return;
    int lo = bounds[drug], hi = bounds[drug + 1];
    float m[8], s[8];
#pragma unroll
    for (int q = 0; q < 8; q++) { m[q] = 0.f; s[q] = 0.f; }
    for (int i = lo; i < hi; i++) {
        uint4 v = ((const uint4*)(x + (size_t)i * D))[lane];
        const __half2* h = (const __half2*)&v;
#pragma unroll
        for (int q = 0; q < 4; q++) {
            float2 f = __half22float2(h[q]);
            m[q * 2]     = fmaxf(m[q * 2], f.x);
            m[q * 2 + 1] = fmaxf(m[q * 2 + 1], f.y);
            s[q * 2]     += f.x;
            s[q * 2 + 1] += f.y;
        }
    }
    float r = 1.f / fmaxf((float)(hi - lo), 1.f);
    uint4 um, us;
    __half2 t0, t1;
    t0 = __float22half2_rn(make_float2(m[0], m[1]));
    t1 = __float22half2_rn(make_float2(m[2], m[3]));
    um.x = *(uint32_t*)&t0; um.y = *(uint32_t*)&t1;
    t0 = __float22half2_rn(make_float2(m[4], m[5]));
    t1 = __float22half2_rn(make_float2(m[6], m[7]));
    um.z = *(uint32_t*)&t0; um.w = *(uint32_t*)&t1;
    t0 = __float22half2_rn(make_float2(s[0] * r, s[1] * r));
    t1 = __float22half2_rn(make_float2(s[2] * r, s[3] * r));
    us.x = *(uint32_t*)&t0; us.y = *(uint32_t*)&t1;
    t0 = __float22half2_rn(make_float2(s[4] * r, s[5] * r));
    t1 = __float22half2_rn(make_float2(s[6] * r, s[7] * r));
    us.z = *(uint32_t*)&t0; us.w = *(uint32_t*)&t1;
    ((uint4*)(gmax + (size_t)drug * D))[lane] = um;
    ((uint4*)(gmean + (size_t)drug * D))[lane] = us;
}

// ---------------- launch --------------------------------------------------------
extern "C" void kernel_launch(void* const* d_in, const int* in_sizes, int n_in,
                              void* d_out, int out_size) {
    const int* x1    = (const int*)d_in[0];
    const int* ei1   = (const int*)d_in[1];
    const int* batch = (const int*)d_in[2];
    const int* x2ids = (const int*)d_in[3];
    const int* ei2   = (const int*)d_in[4];
    const float* emb1  = (const float*)d_in[5];
    const float* emb2  = (const float*)d_in[6];
    const float* Wl1   = (const float*)d_in[7];
    const float* bl1   = (const float*)d_in[8];
    const float* Wr1   = (const float*)d_in[9];
    const float* lin1W = (const float*)d_in[10];
    const float* lin1b = (const float*)d_in[11];
    const float* Wl2   = (const float*)d_in[12];
    const float* bl2   = (const float*)d_in[13];
    const float* Wr2   = (const float*)d_in[14];
    const float* Wx2   = (const float*)d_in[15];

    const int* src1 = ei1;
    const int* dst1 = ei1 + E1C;
    const int* src2 = ei2;
    const int* dst2 = ei2 + E2C;

    __half *x, *y, *agg, *gmax, *gmean, *xdrug, *x2a, *x2b, *agg2, *wt;
    int *cnt1i, *base1, *cur1, *csr1, *part1;
    int *cnt2i, *base2, *cur2, *csr2, *part2, *bounds;
    cudaGetSymbolAddress((void**)&x, h_x);
    cudaGetSymbolAddress((void**)&y, h_y);
    cudaGetSymbolAddress((void**)&agg, h_agg);
    cudaGetSymbolAddress((void**)&gmax, h_gmax);
    cudaGetSymbolAddress((void**)&gmean, h_gmean);
    cudaGetSymbolAddress((void**)&xdrug, h_xdrug);
    cudaGetSymbolAddress((void**)&x2a, h_x2a);
    cudaGetSymbolAddress((void**)&x2b, h_x2b);
    cudaGetSymbolAddress((void**)&agg2, h_agg2);
    cudaGetSymbolAddress((void**)&wt, h_wt);
    cudaGetSymbolAddress((void**)&cnt1i, g_cnt1i);
    cudaGetSymbolAddress((void**)&base1, g_base1);
    cudaGetSymbolAddress((void**)&cur1, g_cur1);
    cudaGetSymbolAddress((void**)&csr1, g_csr1);
    cudaGetSymbolAddress((void**)&part1, g_part1);
    cudaGetSymbolAddress((void**)&cnt2i, g_cnt2i);
    cudaGetSymbolAddress((void**)&base2, g_base2);
    cudaGetSymbolAddress((void**)&cur2, g_cur2);
    cudaGetSymbolAddress((void**)&csr2, g_csr2);
    cudaGetSymbolAddress((void**)&part2, g_part2);
    cudaGetSymbolAddress((void**)&bounds, g_bounds);

    cudaFuncSetAttribute(gemm_h, cudaFuncAttributeMaxDynamicSharedMemorySize, GEMM_SMEM);

    cudaStream_t s = 0;

    // ---- weight transposes (fp32 -> fp16), once per call ----
    WTP wp;
    for (int i = 0; i < 3; i++) { wp.src[i]     = Wl1 + (size_t)i * DD; }
    for (int i = 0; i < 3; i++) { wp.src[3 + i] = Wr1 + (size_t)i * DD; }
    wp.src[6] = lin1W;
    wp.src[7] = lin1W + (size_t)DD;
    for (int i = 0; i < 2; i++) { wp.src[8 + i]  = Wl2 + (size_t)i * DD; }
    for (int i = 0; i < 2; i++) { wp.src[10 + i] = Wr2 + (size_t)i * DD; }
    for (int i = 0; i < 2; i++) { wp.src[12 + i] = Wx2 + (size_t)i * DD; }
    for (int i = 0; i < 14; i++) wp.dst[i] = wt + (size_t)i * DD;
    transpose_h<<<dim3(8, 8, 14), dim3(32, 8), 0, s>>>(wp);

    // ---- CSR build for both graphs ----
    const int nb1 = (N1C + 1023) / 1024;
    const int nb2 = (NDRUG + 1023) / 1024;
    cudaMemsetAsync(cnt1i, 0, N1C * sizeof(int), s);
    cudaMemsetAsync(cnt2i, 0, NDRUG * sizeof(int), s);
    count_int<<<(E1C + 255) / 256, 256, 0, s>>>(dst1, cnt1i, E1C);
    count_int<<<(E2C + 255) / 256, 256, 0, s>>>(dst2, cnt2i, E2C);
    scan_block<<<nb1, 1024, 0, s>>>(cnt1i, base1, part1, N1C);
    scan_block<<<nb2, 1024, 0, s>>>(cnt2i, base2, part2, NDRUG);
    scan_partial<<<1, 128, 0, s>>>(part1, base1 + N1C, nb1);
    scan_partial<<<1, 128, 0, s>>>(part2, base2 + NDRUG, nb2);
    add_offsets<<<nb1, 1024, 0, s>>>(base1, cur1, part1, N1C);
    add_offsets<<<nb2, 1024, 0, s>>>(base2, cur2, part2, NDRUG);
    fill_csr<<<(E1C + 255) / 256, 256, 0, s>>>(src1, dst1, cur1, csr1, E1C);
    fill_csr<<<(E2C + 255) / 256, 256, 0, s>>>(src2, dst2, cur2, csr2, E2C);
    seg_bounds<<<(NDRUG + 1 + 255) / 256, 256, 0, s>>>(batch, bounds, N1C, NDRUG);

    // ---- level 1 ----
    gather_rows_h<<<((size_t)N1C * 64 + 255) / 256, 256, 0, s>>>(emb1, x1, x, N1C);

    __half* xin = x;
    __half* xout = y;
    const dim3 gg1(2, (N1C + 127) / 128);
    for (int i = 0; i < 3; i++) {
        aggregate_h<<<(N1C + 7) / 8, 256, 0, s>>>(xin, csr1, base1, agg, N1C);
        gemm_h<<<gg1, 256, GEMM_SMEM, s>>>(
            agg, wt + (size_t)i * DD,
            xin, wt + (size_t)(3 + i) * DD,
            nullptr, nullptr,
            bl1 + (size_t)i * D, nullptr, xout, N1C, 2);
        __half* t = xin; xin = xout; xout = t;
    }

    // ---- pooling + lin1 ----
    pool2_h<<<NDRUG / 8, 256, 0, s>>>(xin, bounds, gmax, gmean);
    gemm_h<<<dim3(2, NDRUG / 128), 256, GEMM_SMEM, s>>>(
        gmax, wt + (size_t)6 * DD,
        gmean, wt + (size_t)7 * DD,
        nullptr, nullptr,
        lin1b, nullptr, xdrug, NDRUG, 2);

    // ---- level 2 ----
    gather2_h<<<((size_t)NDRUG * 32 + 255) / 256, 256, 0, s>>>(xdrug, emb2, x2ids, x2a);
    __half* x2in = x2a;
    for (int i = 0; i < 2; i++) {
        aggregate_h<<<(NDRUG + 7) / 8, 256, 0, s>>>(x2in, csr2, base2, agg2, NDRUG);
        if (i == 1) {
            gemm_h<<<dim3(2, NDRUG / 128), 256, GEMM_SMEM, s>>>(
                agg2, wt + (size_t)(8 + i) * DD,
                x2in, wt + (size_t)(10 + i) * DD,
                xdrug, wt + (size_t)(12 + i) * DD,
                bl2 + (size_t)i * D, (float*)d_out, nullptr, NDRUG, 3);
        } else {
            gemm_h<<<dim3(2, NDRUG / 128), 256, GEMM_SMEM, s>>>(
                agg2, wt + (size_t)(8 + i) * DD,
                x2in, wt + (size_t)(10 + i) * DD,
                xdrug, wt + (size_t)(12 + i) * DD,
                bl2 + (size_t)i * D, nullptr, x2b, NDRUG, 3);
        }
        x2in = x2b;
    }
}

// round 7
// speedup vs baseline: 8.6196x; 1.0693x over previous
#include <cuda_runtime.h>
#include <cuda_fp16.h>
#include <cstdint>

#define D      256
#define N1C    50000
#define E1C    800000
#define NDRUG  4096
#define E2C    131072
#define DD     (D*D)

#define NB1 ((N1C + 1023) / 1024)     // 49
#define NB2 ((NDRUG + 1023) / 1024)   // 4
#define NBSEG ((NDRUG + 1 + 1023) / 1024)  // 5

// ---------------- scratch (device globals; no allocation allowed) -------------
__device__ __half h_x[(size_t)N1C * D];
__device__ __half h_y[(size_t)N1C * D];
__device__ __half h_agg[(size_t)N1C * D];
__device__ __half h_gmax[NDRUG * D];
__device__ __half h_gmean[NDRUG * D];
__device__ __half h_xdrug[NDRUG * D];
__device__ __half h_x2a[NDRUG * D];
__device__ __half h_x2b[NDRUG * D];
__device__ __half h_agg2[NDRUG * D];
__device__ __half h_wt[14 * DD];          // transposed fp16 weights [N][K]

__device__ int g_cnt1i[N1C];              // self-zeroing (scan zeroes after read)
__device__ int g_base1[N1C + 1];
__device__ int g_cur1[N1C];
__device__ int g_csr1[E1C];
__device__ int g_part1[64];

__device__ int g_cnt2i[NDRUG];            // self-zeroing
__device__ int g_base2[NDRUG + 1];
__device__ int g_cur2[NDRUG];
__device__ int g_csr2[E2C];
__device__ int g_part2[64];

__device__ int g_bounds[NDRUG + 1];

// ---------------- PTX helpers --------------------------------------------------
__device__ __forceinline__ void cp_async_z(uint32_t sa, const void* g, int sz) {
    asm volatile("cp.async.cg.shared.global [%0], [%1], 16, %2;"
                 :: "r"(sa), "l"(g), "r"(sz));
}
#define CP_COMMIT() asm volatile("cp.async.commit_group;" ::: "memory")
#define CP_WAIT0()  asm volatile("cp.async.wait_group 0;" ::: "memory")

__device__ __forceinline__ void ldm_x4(uint32_t* r, uint32_t addr) {
    asm volatile("ldmatrix.sync.aligned.m8n8.x4.shared.b16 {%0,%1,%2,%3}, [%4];"
                 : "=r"(r[0]), "=r"(r[1]), "=r"(r[2]), "=r"(r[3]) : "r"(addr));
}
__device__ __forceinline__ void ldm_x2(uint32_t* r, uint32_t addr) {
    asm volatile("ldmatrix.sync.aligned.m8n8.x2.shared.b16 {%0,%1}, [%2];"
                 : "=r"(r[0]), "=r"(r[1]) : "r"(addr));
}
__device__ __forceinline__ void mma_f16(float* c, const uint32_t* a, const uint32_t* b) {
    asm volatile(
        "mma.sync.aligned.m16n8k16.row.col.f32.f16.f16.f32 "
        "{%0,%1,%2,%3}, {%4,%5,%6,%7}, {%8,%9}, {%0,%1,%2,%3};"
        : "+f"(c[0]), "+f"(c[1]), "+f"(c[2]), "+f"(c[3])
        : "r"(a[0]), "r"(a[1]), "r"(a[2]), "r"(a[3]), "r"(b[0]), "r"(b[1]));
}

// ---------------- fp16 tensor-core GEMM ----------------------------------------
// C[M,256] = relu( sum_s A_s[M,256] @ B_s^T + bias ), A fp16, B fp16 [N][K].
// BM=128, BN=128, BK=32; 256 threads; warps 2(M) x 4(N); warp tile 64x32.
#define ROWB 80
#define TILE_B (128 * ROWB)
#define GEMM_SMEM (4 * TILE_B)

__global__ void __launch_bounds__(256, 2) gemm_h(
    const __half* A0, const __half* B0,
    const __half* A1, const __half* B1,
    const __half* A2, const __half* B2,
    const float* __restrict__ bias,
    float* __restrict__ Cf, __half* __restrict__ Ch, int M, int nseg) {
    extern __shared__ char sm[];
    const uint32_t smBase = (uint32_t)__cvta_generic_to_shared(sm);
    const uint32_t aBase[2] = { smBase, smBase + TILE_B };
    const uint32_t bBase[2] = { smBase + 2 * TILE_B, smBase + 3 * TILE_B };

    const int tid = threadIdx.x;
    const int wid = tid >> 5;
    const int lane = tid & 31;
    const int g = lane >> 2;
    const int tq = lane & 3;
    const int wm = (wid >> 2) * 64;
    const int wn = (wid & 3) * 32;
    const int m0 = blockIdx.y * 128;
    const int n0 = blockIdx.x * 128;

    uint32_t aoff[4], boff[4];
#pragma unroll
    for (int mt = 0; mt < 4; mt++)
        aoff[mt] = (uint32_t)((wm + mt * 16 + (lane & 15)) * ROWB + ((lane & 16) ? 16 : 0));
#pragma unroll
    for (int nt = 0; nt < 4; nt++)
        boff[nt] = (uint32_t)((wn + nt * 8 + (lane & 7)) * ROWB + ((lane & 8) ? 16 : 0));

    float acc[4][4][4];
#pragma unroll
    for (int mt = 0; mt < 4; mt++)
#pragma unroll
        for (int nt = 0; nt < 4; nt++)
#pragma unroll
            for (int q = 0; q < 4; q++) acc[mt][nt][q] = 0.f;

    const __half* Aseg[3] = { A0, A1, A2 };
    const __half* Bseg[3] = { B0, B1, B2 };
    const int total = nseg * 8;

    const int c0i = tid * 2;
    const int row0 = c0i >> 2, off0 = (c0i & 3) * 16;
    const int row1 = (c0i + 1) >> 2, off1 = ((c0i + 1) & 3) * 16;

#define STAGE(buf, tile) do { \
    const __half* A = Aseg[(tile) >> 3]; \
    const __half* B = Bseg[(tile) >> 3]; \
    const int kh = ((tile) & 7) * 32; \
    cp_async_z(aBase[buf] + row0 * ROWB + off0, \
               (const char*)(A + (size_t)(m0 + row0) * D + kh) + off0, \
               (m0 + row0 < M) ? 16 : 0); \
    cp_async_z(aBase[buf] + row1 * ROWB + off1, \
               (const char*)(A + (size_t)(m0 + row1) * D + kh) + off1, \
               (m0 + row1 < M) ? 16 : 0); \
    cp_async_z(bBase[buf] + row0 * ROWB + off0, \
               (const char*)(B + (size_t)(n0 + row0) * D + kh) + off0, 16); \
    cp_async_z(bBase[buf] + row1 * ROWB + off1, \
               (const char*)(B + (size_t)(n0 + row1) * D + kh) + off1, 16); \
    CP_COMMIT(); \
} while (0)

    STAGE(0, 0);
    CP_WAIT0();
    __syncthreads();

    for (int t = 0; t < total; t++) {
        const int buf = t & 1;
        if (t + 1 < total) STAGE(buf ^ 1, t + 1);

        const uint32_t Ab = aBase[buf], Bb = bBase[buf];
#pragma unroll
        for (int ks = 0; ks < 2; ks++) {
            uint32_t af[4][4], bf[4][2];
#pragma unroll
            for (int mt = 0; mt < 4; mt++) ldm_x4(af[mt], Ab + aoff[mt] + ks * 32);
#pragma unroll
            for (int nt = 0; nt < 4; nt++) ldm_x2(bf[nt], Bb + boff[nt] + ks * 32);
#pragma unroll
            for (int mt = 0; mt < 4; mt++)
#pragma unroll
                for (int nt = 0; nt < 4; nt++)
                    mma_f16(acc[mt][nt], af[mt], bf[nt]);
        }

        if (t + 1 < total) {
            CP_WAIT0();
            __syncthreads();
        }
    }

#pragma unroll
    for (int mt = 0; mt < 4; mt++) {
        int mlo = m0 + wm + mt * 16 + g;
#pragma unroll
        for (int nt = 0; nt < 4; nt++) {
            int n = n0 + wn + nt * 8 + tq * 2;
            float b0 = bias[n], b1 = bias[n + 1];
            float o0 = fmaxf(acc[mt][nt][0] + b0, 0.f);
            float o1 = fmaxf(acc[mt][nt][1] + b1, 0.f);
            float o2 = fmaxf(acc[mt][nt][2] + b0, 0.f);
            float o3 = fmaxf(acc[mt][nt][3] + b1, 0.f);
            if (Ch) {
                if (mlo < M)
                    *(__half2*)(Ch + (size_t)mlo * D + n) =
                        __float22half2_rn(make_float2(o0, o1));
                if (mlo + 8 < M)
                    *(__half2*)(Ch + (size_t)(mlo + 8) * D + n) =
                        __float22half2_rn(make_float2(o2, o3));
            } else {
                if (mlo < M)
                    *(float2*)(Cf + (size_t)mlo * D + n) = make_float2(o0, o1);
                if (mlo + 8 < M)
                    *(float2*)(Cf + (size_t)(mlo + 8) * D + n) = make_float2(o2, o3);
            }
        }
    }
}

// ---------------- weight transpose (fp32 -> fp16, [K][N] -> [N][K]) ------------
struct WTP { const float* src[14]; __half* dst[14]; };

__global__ void transpose_h(WTP p) {
    __shared__ float t[32][33];
    const float* src = p.src[blockIdx.z];
    __half* dst = p.dst[blockIdx.z];
    int x = blockIdx.x * 32 + threadIdx.x;
    int y0 = blockIdx.y * 32 + threadIdx.y;
#pragma unroll
    for (int i = 0; i < 32; i += 8)
        t[threadIdx.y + i][threadIdx.x] = src[(size_t)(y0 + i) * D + x];
    __syncthreads();
    int x2 = blockIdx.y * 32 + threadIdx.x;
    int y2 = blockIdx.x * 32 + threadIdx.y;
#pragma unroll
    for (int i = 0; i < 32; i += 8)
        dst[(size_t)(y2 + i) * D + x2] = __float2half_rn(t[threadIdx.x][threadIdx.y + i]);
}

// ---------------- merged CSR-build kernels -------------------------------------
// one kernel counts both graphs' in-degrees
__global__ void count_both(const int* __restrict__ dst1, const int* __restrict__ dst2,
                           int* __restrict__ cnt1, int* __restrict__ cnt2) {
    int e = blockIdx.x * blockDim.x + threadIdx.x;
    if (e < E1C) {
        atomicAdd(&cnt1[dst1[e]], 1);
    } else {
        e -= E1C;
        if (e < E2C) atomicAdd(&cnt2[dst2[e]], 1);
    }
}

// block-range dispatch scan over both counter arrays; zeroes cnt after read
// (self-zeroing: next graph replay sees zeros, first call sees BSS zeros)
__global__ void __launch_bounds__(1024) scan_block_both(
    int* __restrict__ cnt1, int* __restrict__ out1, int* __restrict__ part1,
    int* __restrict__ cnt2, int* __restrict__ out2, int* __restrict__ part2) {
    __shared__ int ws[32];
    int* cnt; int* out; int* partial; int n, b;
    if (blockIdx.x < NB1) { cnt = cnt1; out = out1; partial = part1; n = N1C; b = blockIdx.x; }
    else { cnt = cnt2; out = out2; partial = part2; n = NDRUG; b = blockIdx.x - NB1; }
    int i = b * 1024 + threadIdx.x;
    int lane = threadIdx.x & 31, w = threadIdx.x >> 5;
    int v = 0;
    if (i < n) { v = cnt[i]; cnt[i] = 0; }
    int x = v;
#pragma unroll
    for (int o = 1; o < 32; o <<= 1) {
        int y = __shfl_up_sync(0xffffffffu, x, o);
        if (lane >= o) x += y;
    }
    if (lane == 31) ws[w] = x;
    __syncthreads();
    if (w == 0) {
        int t = ws[lane];
#pragma unroll
        for (int o = 1; o < 32; o <<= 1) {
            int y = __shfl_up_sync(0xffffffffu, t, o);
            if (lane >= o) t += y;
        }
        ws[lane] = t;
    }
    __syncthreads();
    int excl = x - v + (w ? ws[w - 1] : 0);
    if (i < n) out[i] = excl;
    if (threadIdx.x == 1023) partial[b] = excl + v;
}

// 2 blocks: block 0 scans part1, block 1 scans part2
__global__ void __launch_bounds__(128) scan_partial_both(
    int* __restrict__ part1, int* __restrict__ t1,
    int* __restrict__ part2, int* __restrict__ t2) {
    __shared__ int sh[128];
    int* partial = blockIdx.x ? part2 : part1;
    int* base_n  = blockIdx.x ? t2 : t1;
    int nb       = blockIdx.x ? NB2 : NB1;
    int tid = threadIdx.x;
    int v = (tid < nb) ? partial[tid] : 0;
    sh[tid] = v;
    __syncthreads();
#pragma unroll
    for (int o = 1; o < 128; o <<= 1) {
        int t = (tid >= o) ? sh[tid - o] : 0;
        __syncthreads();
        sh[tid] += t;
        __syncthreads();
    }
    if (tid < nb) partial[tid] = sh[tid] - v;
    if (tid == 127) *base_n = sh[127];
}

// add partial offsets (writes base + cur) for both graphs, plus seg_bounds blocks
__global__ void __launch_bounds__(1024) add_offsets_both(
    int* __restrict__ base1, int* __restrict__ cur1, const int* __restrict__ part1,
    int* __restrict__ base2, int* __restrict__ cur2, const int* __restrict__ part2,
    const int* __restrict__ batch, int* __restrict__ bounds) {
    if (blockIdx.x < NB1) {
        int i = blockIdx.x * 1024 + threadIdx.x;
        if (i < N1C) {
            int v = base1[i] + part1[blockIdx.x];
            base1[i] = v;
            cur1[i] = v;
        }
    } else if (blockIdx.x < NB1 + NB2) {
        int b = blockIdx.x - NB1;
        int i = b * 1024 + threadIdx.x;
        if (i < NDRUG) {
            int v = base2[i] + part2[b];
            base2[i] = v;
            cur2[i] = v;
        }
    } else {
        int b = blockIdx.x - NB1 - NB2;
        int q = b * 1024 + threadIdx.x;
        if (q <= NDRUG) {
            int lo = 0, hi = N1C;
            while (lo < hi) {
                int mid = (lo + hi) >> 1;
                if (batch[mid] < q) lo = mid + 1; else hi = mid;
            }
            bounds[q] = lo;
        }
    }
}

// fill both CSR arrays
__global__ void fill_both(const int* __restrict__ src1, const int* __restrict__ dst1,
                          int* __restrict__ cur1, int* __restrict__ csr1,
                          const int* __restrict__ src2, const int* __restrict__ dst2,
                          int* __restrict__ cur2, int* __restrict__ csr2) {
    int e = blockIdx.x * blockDim.x + threadIdx.x;
    if (e < E1C) {
        int p = atomicAdd(&cur1[dst1[e]], 1);
        csr1[p] = src1[e];
    } else {
        e -= E1C;
        if (e < E2C) {
            int p = atomicAdd(&cur2[dst2[e]], 1);
            csr2[p] = src2[e];
        }
    }
}

// ---------------- small kernels -------------------------------------------------
__global__ void gather_rows_h(const float* __restrict__ emb, const int* __restrict__ ids,
                              __half* __restrict__ out, int n) {
    int t = blockIdx.x * blockDim.x + threadIdx.x;
    int i = t >> 6, c = t & 63;
    if (i >= n) return;
    float4 v = ((const float4*)(emb + (size_t)ids[i] * D))[c];
    __half2 h0 = __float22half2_rn(make_float2(v.x, v.y));
    __half2 h1 = __float22half2_rn(make_float2(v.z, v.w));
    uint2 u;
    u.x = *(uint32_t*)&h0;
    u.y = *(uint32_t*)&h1;
    ((uint2*)(out + (size_t)i * D))[c] = u;
}

__global__ void gather2_h(const __half* __restrict__ xdrug, const float* __restrict__ emb2,
                          const int* __restrict__ ids, __half* __restrict__ out) {
    int t = blockIdx.x * blockDim.x + threadIdx.x;
    int i = t >> 5, c = t & 31;
    if (i >= NDRUG) return;
    int id = ids[i];
    uint4 u;
    if (id < NDRUG) {
        u = ((const uint4*)(xdrug + (size_t)id * D))[c];
    } else {
        const float4* r = (const float4*)(emb2 + (size_t)id * D);
        float4 a = r[c * 2], b = r[c * 2 + 1];
        __half2 h0 = __float22half2_rn(make_float2(a.x, a.y));
        __half2 h1 = __float22half2_rn(make_float2(a.z, a.w));
        __half2 h2 = __float22half2_rn(make_float2(b.x, b.y));
        __half2 h3 = __float22half2_rn(make_float2(b.z, b.w));
        u.x = *(uint32_t*)&h0; u.y = *(uint32_t*)&h1;
        u.z = *(uint32_t*)&h2; u.w = *(uint32_t*)&h3;
    }
    ((uint4*)(out + (size_t)i * D))[c] = u;
}

// warp-per-node mean aggregation (fp16 in/out, fp32 accumulate), 4-edge unroll
__global__ void __launch_bounds__(256) aggregate_h(
    const __half* __restrict__ x, const int* __restrict__ csr,
    const int* __restrict__ base, __half* __restrict__ agg, int n) {
    int node = blockIdx.x * 8 + (threadIdx.x >> 5);
    int lane = threadIdx.x & 31;
    if (node >= n) return;
    int lo = base[node], hi = base[node + 1];
    float2 a0 = make_float2(0.f, 0.f), a1 = a0, a2 = a0, a3 = a0;
    int j = lo;
#define ACCUM(V) do { \
    float2 f; \
    f = __half22float2(*(__half2*)&(V).x); a0.x += f.x; a0.y += f.y; \
    f = __half22float2(*(__half2*)&(V).y); a1.x += f.x; a1.y += f.y; \
    f = __half22float2(*(__half2*)&(V).z); a2.x += f.x; a2.y += f.y; \
    f = __half22float2(*(__half2*)&(V).w); a3.x += f.x; a3.y += f.y; \
} while (0)
    for (; j + 3 < hi; j += 4) {
        int s0 = csr[j], s1 = csr[j + 1], s2 = csr[j + 2], s3 = csr[j + 3];
        uint4 v0 = ((const uint4*)(x + (size_t)s0 * D))[lane];
        uint4 v1 = ((const uint4*)(x + (size_t)s1 * D))[lane];
        uint4 v2 = ((const uint4*)(x + (size_t)s2 * D))[lane];
        uint4 v3 = ((const uint4*)(x + (size_t)s3 * D))[lane];
        ACCUM(v0); ACCUM(v1); ACCUM(v2); ACCUM(v3);
    }
    for (; j < hi; j++) {
        uint4 v0 = ((const uint4*)(x + (size_t)csr[j] * D))[lane];
        ACCUM(v0);
    }
#undef ACCUM
    float r = 1.f / fmaxf((float)(hi - lo), 1.f);
    __half2 h0 = __float22half2_rn(make_float2(a0.x * r, a0.y * r));
    __half2 h1 = __float22half2_rn(make_float2(a1.x * r, a1.y * r));
    __half2 h2 = __float22half2_rn(make_float2(a2.x * r, a2.y * r));
    __half2 h3 = __float22half2_rn(make_float2(a3.x * r, a3.y * r));
    uint4 u;
    u.x = *(uint32_t*)&h0; u.y = *(uint32_t*)&h1;
    u.z = *(uint32_t*)&h2; u.w = *(uint32_t*)&h3;
    ((uint4*)(agg + (size_t)node * D))[lane] = u;
}

// warp-per-drug max + mean pooling (fp16 in, fp16 out, fp32 math)
__global__ void __launch_bounds__(256) pool2_h(
    const __half* __restrict__ x, const int* __restrict__ bounds,
    __half* __restrict__ gmax, __half* __restrict__ gmean) {
    int drug = blockIdx.x * 8 + (threadIdx.x >> 5);
    int lane = threadIdx.x & 31;
    if (drug >= NDRUG) return;
    int lo = bounds[drug], hi = bounds[drug + 1];
    float m[8], s[8];
#pragma unroll
    for (int q = 0; q < 8; q++) { m[q] = 0.f; s[q] = 0.f; }
    for (int i = lo; i < hi; i++) {
        uint4 v = ((const uint4*)(x + (size_t)i * D))[lane];
        const __half2* h = (const __half2*)&v;
#pragma unroll
        for (int q = 0; q < 4; q++) {
            float2 f = __half22float2(h[q]);
            m[q * 2]     = fmaxf(m[q * 2], f.x);
            m[q * 2 + 1] = fmaxf(m[q * 2 + 1], f.y);
            s[q * 2]     += f.x;
            s[q * 2 + 1] += f.y;
        }
    }
    float r = 1.f / fmaxf((float)(hi - lo), 1.f);
    uint4 um, us;
    __half2 t0, t1;
    t0 = __float22half2_rn(make_float2(m[0], m[1]));
    t1 = __float22half2_rn(make_float2(m[2], m[3]));
    um.x = *(uint32_t*)&t0; um.y = *(uint32_t*)&t1;
    t0 = __float22half2_rn(make_float2(m[4], m[5]));
    t1 = __float22half2_rn(make_float2(m[6], m[7]));
    um.z = *(uint32_t*)&t0; um.w = *(uint32_t*)&t1;
    t0 = __float22half2_rn(make_float2(s[0] * r, s[1] * r));
    t1 = __float22half2_rn(make_float2(s[2] * r, s[3] * r));
    us.x = *(uint32_t*)&t0; us.y = *(uint32_t*)&t1;
    t0 = __float22half2_rn(make_float2(s[4] * r, s[5] * r));
    t1 = __float22half2_rn(make_float2(s[6] * r, s[7] * r));
    us.z = *(uint32_t*)&t0; us.w = *(uint32_t*)&t1;
    ((uint4*)(gmax + (size_t)drug * D))[lane] = um;
    ((uint4*)(gmean + (size_t)drug * D))[lane] = us;
}

// ---------------- launch --------------------------------------------------------
extern "C" void kernel_launch(void* const* d_in, const int* in_sizes, int n_in,
                              void* d_out, int out_size) {
    const int* x1    = (const int*)d_in[0];
    const int* ei1   = (const int*)d_in[1];
    const int* batch = (const int*)d_in[2];
    const int* x2ids = (const int*)d_in[3];
    const int* ei2   = (const int*)d_in[4];
    const float* emb1  = (const float*)d_in[5];
    const float* emb2  = (const float*)d_in[6];
    const float* Wl1   = (const float*)d_in[7];
    const float* bl1   = (const float*)d_in[8];
    const float* Wr1   = (const float*)d_in[9];
    const float* lin1W = (const float*)d_in[10];
    const float* lin1b = (const float*)d_in[11];
    const float* Wl2   = (const float*)d_in[12];
    const float* bl2   = (const float*)d_in[13];
    const float* Wr2   = (const float*)d_in[14];
    const float* Wx2   = (const float*)d_in[15];

    const int* src1 = ei1;
    const int* dst1 = ei1 + E1C;
    const int* src2 = ei2;
    const int* dst2 = ei2 + E2C;

    __half *x, *y, *agg, *gmax, *gmean, *xdrug, *x2a, *x2b, *agg2, *wt;
    int *cnt1i, *base1, *cur1, *csr1, *part1;
    int *cnt2i, *base2, *cur2, *csr2, *part2, *bounds;
    cudaGetSymbolAddress((void**)&x, h_x);
    cudaGetSymbolAddress((void**)&y, h_y);
    cudaGetSymbolAddress((void**)&agg, h_agg);
    cudaGetSymbolAddress((void**)&gmax, h_gmax);
    cudaGetSymbolAddress((void**)&gmean, h_gmean);
    cudaGetSymbolAddress((void**)&xdrug, h_xdrug);
    cudaGetSymbolAddress((void**)&x2a, h_x2a);
    cudaGetSymbolAddress((void**)&x2b, h_x2b);
    cudaGetSymbolAddress((void**)&agg2, h_agg2);
    cudaGetSymbolAddress((void**)&wt, h_wt);
    cudaGetSymbolAddress((void**)&cnt1i, g_cnt1i);
    cudaGetSymbolAddress((void**)&base1, g_base1);
    cudaGetSymbolAddress((void**)&cur1, g_cur1);
    cudaGetSymbolAddress((void**)&csr1, g_csr1);
    cudaGetSymbolAddress((void**)&part1, g_part1);
    cudaGetSymbolAddress((void**)&cnt2i, g_cnt2i);
    cudaGetSymbolAddress((void**)&base2, g_base2);
    cudaGetSymbolAddress((void**)&cur2, g_cur2);
    cudaGetSymbolAddress((void**)&csr2, g_csr2);
    cudaGetSymbolAddress((void**)&part2, g_part2);
    cudaGetSymbolAddress((void**)&bounds, g_bounds);

    cudaFuncSetAttribute(gemm_h, cudaFuncAttributeMaxDynamicSharedMemorySize, GEMM_SMEM);

    cudaStream_t s = 0;

    // ---- weight transposes (fp32 -> fp16), once per call ----
    WTP wp;
    for (int i = 0; i < 3; i++) { wp.src[i]     = Wl1 + (size_t)i * DD; }
    for (int i = 0; i < 3; i++) { wp.src[3 + i] = Wr1 + (size_t)i * DD; }
    wp.src[6] = lin1W;
    wp.src[7] = lin1W + (size_t)DD;
    for (int i = 0; i < 2; i++) { wp.src[8 + i]  = Wl2 + (size_t)i * DD; }
    for (int i = 0; i < 2; i++) { wp.src[10 + i] = Wr2 + (size_t)i * DD; }
    for (int i = 0; i < 2; i++) { wp.src[12 + i] = Wx2 + (size_t)i * DD; }
    for (int i = 0; i < 14; i++) wp.dst[i] = wt + (size_t)i * DD;
    transpose_h<<<dim3(8, 8, 14), dim3(32, 8), 0, s>>>(wp);

    // ---- CSR build for both graphs (counters self-zeroed by scan kernel) ----
    const int eboth = (E1C + E2C + 255) / 256;
    count_both<<<eboth, 256, 0, s>>>(dst1, dst2, cnt1i, cnt2i);
    scan_block_both<<<NB1 + NB2, 1024, 0, s>>>(cnt1i, base1, part1, cnt2i, base2, part2);
    scan_partial_both<<<2, 128, 0, s>>>(part1, base1 + N1C, part2, base2 + NDRUG);
    add_offsets_both<<<NB1 + NB2 + NBSEG, 1024, 0, s>>>(
        base1, cur1, part1, base2, cur2, part2, batch, bounds);
    fill_both<<<eboth, 256, 0, s>>>(src1, dst1, cur1, csr1, src2, dst2, cur2, csr2);

    // ---- level 1 ----
    gather_rows_h<<<((size_t)N1C * 64 + 255) / 256, 256, 0, s>>>(emb1, x1, x, N1C);

    __half* xin = x;
    __half* xout = y;
    const dim3 gg1(2, (N1C + 127) / 128);
    for (int i = 0; i < 3; i++) {
        aggregate_h<<<(N1C + 7) / 8, 256, 0, s>>>(xin, csr1, base1, agg, N1C);
        gemm_h<<<gg1, 256, GEMM_SMEM, s>>>(
            agg, wt + (size_t)i * DD,
            xin, wt + (size_t)(3 + i) * DD,
            nullptr, nullptr,
            bl1 + (size_t)i * D, nullptr, xout, N1C, 2);
        __half* t = xin; xin = xout; xout = t;
    }

    // ---- pooling + lin1 ----
    pool2_h<<<NDRUG / 8, 256, 0, s>>>(xin, bounds, gmax, gmean);
    gemm_h<<<dim3(2, NDRUG / 128), 256, GEMM_SMEM, s>>>(
        gmax, wt + (size_t)6 * DD,
        gmean, wt + (size_t)7 * DD,
        nullptr, nullptr,
        lin1b, nullptr, xdrug, NDRUG, 2);

    // ---- level 2 ----
    gather2_h<<<((size_t)NDRUG * 32 + 255) / 256, 256, 0, s>>>(xdrug, emb2, x2ids, x2a);
    __half* x2in = x2a;
    for (int i = 0; i < 2; i++) {
        aggregate_h<<<(NDRUG + 7) / 8, 256, 0, s>>>(x2in, csr2, base2, agg2, NDRUG);
        if (i == 1) {
            gemm_h<<<dim3(2, NDRUG / 128), 256, GEMM_SMEM, s>>>(
                agg2, wt + (size_t)(8 + i) * DD,
                x2in, wt + (size_t)(10 + i) * DD,
                xdrug, wt + (size_t)(12 + i) * DD,
                bl2 + (size_t)i * D, (float*)d_out, nullptr, NDRUG, 3);
        } else {
            gemm_h<<<dim3(2, NDRUG / 128), 256, GEMM_SMEM, s>>>(
                agg2, wt + (size_t)(8 + i) * DD,
                x2in, wt + (size_t)(10 + i) * DD,
                xdrug, wt + (size_t)(12 + i) * DD,
                bl2 + (size_t)i * D, nullptr, x2b, NDRUG, 3);
        }
        x2in = x2b;
    }
}